// round 11
// baseline (speedup 1.0000x reference)
#include <cuda_runtime.h>
#include <cuda_bf16.h>
#include <math.h>
#include <stdint.h>

#define BBATCH 4
#define SS 512
#define EE 512
#define HH 64
#define FFNN 2048
#define MROWS 2048
#define QKVN 1536

typedef __nv_bfloat16 bf16;
typedef __nv_bfloat162 bf162;

// ---------------- scratch (__device__ globals; no allocations allowed) ----------------
__device__ bf16  g_proj_h[MROWS*EE];
__device__ bf16  g_proj_l[MROWS*EE];
__device__ float g_qkv  [MROWS*QKVN];
__device__ bf16  g_ctx_h[MROWS*EE];
__device__ bf16  g_ctx_l[MROWS*EE];
__device__ float g_x1f  [MROWS*EE];
__device__ bf16  g_x1_h [MROWS*EE];
__device__ bf16  g_x1_l [MROWS*EE];
__device__ bf16  g_hh   [MROWS*FFNN];
__device__ bf16  g_hl   [MROWS*FFNN];
__device__ float g_t0   [MROWS*EE];
#define W_INW  0
#define W_OUTW (QKVN*EE)
#define W_W1   (W_OUTW + EE*EE)
#define W_W2   (W_W1 + FFNN*EE)
#define W_TOTAL (W_W2 + EE*FFNN)
__device__ bf16  g_wh[W_TOTAL];
__device__ bf16  g_wl[W_TOTAL];

// ---------------- helpers ----------------
__device__ __forceinline__ void split1(float v, bf16& h, bf16& l) {
    h = __float2bfloat16(v);
    l = __float2bfloat16(v - __bfloat162float(h));
}
__device__ __forceinline__ uint32_t smem_u32(const void* p) {
    return (uint32_t)__cvta_generic_to_shared(p);
}
__device__ __forceinline__ void ldm_x4(uint32_t* r, uint32_t addr) {
    asm volatile("ldmatrix.sync.aligned.m8n8.x4.shared.b16 {%0,%1,%2,%3}, [%4];"
                 : "=r"(r[0]), "=r"(r[1]), "=r"(r[2]), "=r"(r[3]) : "r"(addr));
}
__device__ __forceinline__ void mma16816(float* c, const uint32_t* a, const uint32_t* b) {
    asm volatile("mma.sync.aligned.m16n8k16.row.col.f32.bf16.bf16.f32 "
                 "{%0,%1,%2,%3},{%4,%5,%6,%7},{%8,%9},{%0,%1,%2,%3};"
                 : "+f"(c[0]), "+f"(c[1]), "+f"(c[2]), "+f"(c[3])
                 : "r"(a[0]), "r"(a[1]), "r"(a[2]), "r"(a[3]), "r"(b[0]), "r"(b[1]));
}
__device__ __forceinline__ void cpa16(uint32_t dst, const void* src) {
    asm volatile("cp.async.cg.shared.global [%0], [%1], 16;" :: "r"(dst), "l"(src));
}
__device__ __forceinline__ uint32_t pack2(bf16 a, bf16 b) {
    bf162 t{a, b};
    return *reinterpret_cast<uint32_t*>(&t);
}

// ---------------- combined weight split ----------------
__global__ __launch_bounds__(256) void split_all_kernel(
    const float* __restrict__ in_w, const float* __restrict__ out_w,
    const float* __restrict__ w1, const float* __restrict__ w2,
    bf16* __restrict__ h, bf16* __restrict__ l) {
    int i = blockIdx.x * blockDim.x + threadIdx.x;   // float4 index
    if (i >= W_TOTAL / 4) return;
    int e = i * 4;
    const float* src; int off;
    if      (e < W_OUTW) { src = in_w;  off = e; }
    else if (e < W_W1)   { src = out_w; off = e - W_OUTW; }
    else if (e < W_W2)   { src = w1;    off = e - W_W1; }
    else                 { src = w2;    off = e - W_W2; }
    float4 v = *(const float4*)(src + off);
    bf16 h0,h1,h2,h3,l0,l1,l2,l3;
    split1(v.x,h0,l0); split1(v.y,h1,l1); split1(v.z,h2,l2); split1(v.w,h3,l3);
    ((bf162*)h)[i*2+0] = bf162{h0,h1};
    ((bf162*)h)[i*2+1] = bf162{h2,h3};
    ((bf162*)l)[i*2+0] = bf162{l0,l1};
    ((bf162*)l)[i*2+1] = bf162{l2,l3};
}

// ---------------- quantum projection == prefix product of cos ----------------
__global__ __launch_bounds__(256) void proj_kernel(const float* __restrict__ x,
                                                   bf16* __restrict__ ph,
                                                   bf16* __restrict__ pl, int ngroups) {
    int g = blockIdx.x * blockDim.x + threadIdx.x;
    if (g >= ngroups) return;
    const float4* xp = (const float4*)(x + (size_t)g * 8);
    float4 a = xp[0], b = xp[1];
    float r[8];
    r[0] = cosf(a.x);
    r[1] = r[0] * cosf(a.y);
    r[2] = r[1] * cosf(a.z);
    r[3] = r[2] * cosf(a.w);
    r[4] = r[3] * cosf(b.x);
    r[5] = r[4] * cosf(b.y);
    r[6] = r[5] * cosf(b.z);
    r[7] = r[6] * cosf(b.w);
    bf16 h[8], l[8];
#pragma unroll
    for (int i = 0; i < 8; i++) split1(r[i], h[i], l[i]);
    bf162* oh = (bf162*)(ph + (size_t)g * 8);
    bf162* ol = (bf162*)(pl + (size_t)g * 8);
#pragma unroll
    for (int i = 0; i < 4; i++) { oh[i] = bf162{h[2*i],h[2*i+1]}; ol[i] = bf162{l[2*i],l[2*i+1]}; }
}

// ---------------- 3xBF16 mma.sync GEMM: C = A(MxK) @ B(NxK)^T + bias ----------------
template<int MFRAG, int EPI, bool RELU>
__global__ __launch_bounds__(256) void gemm_mma(
    const bf16* __restrict__ Ah, const bf16* __restrict__ Al,
    const bf16* __restrict__ Bh, const bf16* __restrict__ Bl,
    const float* __restrict__ bias,
    float* __restrict__ Cf, bf16* __restrict__ Ch, bf16* __restrict__ Cl,
    int N, int K)
{
    constexpr int BM = MFRAG * 32;
    constexpr int ROWB = 80;
    constexpr int A_SZ = BM * ROWB;
    constexpr int B_SZ = 128 * ROWB;
    constexpr int STAGE = 2 * A_SZ + 2 * B_SZ;

    extern __shared__ char dynsmem[];
    const uint32_t dbase = smem_u32(dynsmem);

    const int tid = threadIdx.x;
    const int lane = tid & 31, wid = tid >> 5;
    const int warp_m = wid >> 2, warp_n = wid & 3;
    const int m_base = warp_m * (MFRAG * 16);
    const int n_base = warp_n * 32;
    const int blockRow = blockIdx.y * BM;
    const int blockCol = blockIdx.x * 128;

    const int lg = lane >> 3, li = lane & 7;
    const int a_row = li + (lg & 1) * 8;
    const int a_col = (lg >> 1) * 8;
    const int b_row = li + (lg >> 1) * 8;
    const int b_col = (lg & 1) * 8;

    float acc[MFRAG][4][4];
#pragma unroll
    for (int mf = 0; mf < MFRAG; mf++)
#pragma unroll
        for (int nf = 0; nf < 4; nf++)
#pragma unroll
            for (int q = 0; q < 4; q++) acc[mf][nf][q] = 0.f;

    auto ld_arr = [&](const bf16* g, int row0, int k0, uint32_t sb, int rows) {
        const int nch = rows * 4;
        for (int c = tid; c < nch; c += 256) {
            int r = c >> 2, seg = c & 3;
            cpa16(sb + (uint32_t)(r * ROWB + seg * 16),
                  g + (size_t)(row0 + r) * K + k0 + seg * 8);
        }
    };
    auto load_chunk = [&](int s, int kt) {
        const uint32_t sb = dbase + (uint32_t)s * STAGE;
        const int k0 = kt * 32;
        ld_arr(Ah, blockRow, k0, sb, BM);
        ld_arr(Al, blockRow, k0, sb + A_SZ, BM);
        ld_arr(Bh, blockCol, k0, sb + 2 * A_SZ, 128);
        ld_arr(Bl, blockCol, k0, sb + 2 * A_SZ + B_SZ, 128);
        asm volatile("cp.async.commit_group;");
    };

    const int T = K / 32;
    load_chunk(0, 0);
    load_chunk(1, 1);
    load_chunk(2, 2);

    for (int it = 0; it < T; ++it) {
        if (it < T - 2)       asm volatile("cp.async.wait_group 2;");
        else if (it == T - 2) asm volatile("cp.async.wait_group 1;");
        else                  asm volatile("cp.async.wait_group 0;");
        __syncthreads();

        const int s = it % 3;
        const uint32_t aH = dbase + (uint32_t)s * STAGE;
        const uint32_t aL = aH + A_SZ;
        const uint32_t bH = aH + 2 * A_SZ;
        const uint32_t bL = bH + B_SZ;

        uint32_t fah[2][MFRAG][4], fal[2][MFRAG][4], fbh[2][2][4], fbl[2][2][4];
#pragma unroll
        for (int j = 0; j < 2; j++) {
#pragma unroll
            for (int mf = 0; mf < MFRAG; mf++) {
                uint32_t ro = (uint32_t)((m_base + mf * 16 + a_row) * ROWB
                                         + (j * 16 + a_col) * 2);
                ldm_x4(fah[j][mf], aH + ro);
                ldm_x4(fal[j][mf], aL + ro);
            }
#pragma unroll
            for (int nt = 0; nt < 2; nt++) {
                uint32_t ro = (uint32_t)((n_base + nt * 16 + b_row) * ROWB
                                         + (j * 16 + b_col) * 2);
                ldm_x4(fbh[j][nt], bH + ro);
                ldm_x4(fbl[j][nt], bL + ro);
            }
        }
#pragma unroll
        for (int j = 0; j < 2; j++) {
#pragma unroll
            for (int mf = 0; mf < MFRAG; mf++) {
#pragma unroll
                for (int nt = 0; nt < 2; nt++) {
#pragma unroll
                    for (int h = 0; h < 2; h++) {
                        const int nf = nt * 2 + h;
                        uint32_t bh2[2] = { fbh[j][nt][2*h], fbh[j][nt][2*h+1] };
                        uint32_t bl2[2] = { fbl[j][nt][2*h], fbl[j][nt][2*h+1] };
                        mma16816(acc[mf][nf], fah[j][mf], bh2);
                        mma16816(acc[mf][nf], fah[j][mf], bl2);
                        mma16816(acc[mf][nf], fal[j][mf], bh2);
                    }
                }
            }
        }

        if (it + 3 < T) {
            __syncthreads();
            load_chunk((it + 3) % 3, it + 3);
        }
    }

#pragma unroll
    for (int mf = 0; mf < MFRAG; mf++) {
        const int r0 = blockRow + m_base + mf * 16 + (lane >> 2);
#pragma unroll
        for (int nf = 0; nf < 4; nf++) {
            const int col = blockCol + n_base + nf * 8 + ((lane & 3) << 1);
            const float2 bv = *(const float2*)(bias + col);
            float v0 = acc[mf][nf][0] + bv.x;
            float v1 = acc[mf][nf][1] + bv.y;
            float v2 = acc[mf][nf][2] + bv.x;
            float v3 = acc[mf][nf][3] + bv.y;
            if (RELU) {
                v0 = fmaxf(v0, 0.f); v1 = fmaxf(v1, 0.f);
                v2 = fmaxf(v2, 0.f); v3 = fmaxf(v3, 0.f);
            }
            if (EPI == 0) {
                *(float2*)(Cf + (size_t)r0 * N + col)       = make_float2(v0, v1);
                *(float2*)(Cf + (size_t)(r0 + 8) * N + col) = make_float2(v2, v3);
            } else {
                bf16 h0,h1,h2,h3,l0,l1,l2,l3;
                split1(v0,h0,l0); split1(v1,h1,l1); split1(v2,h2,l2); split1(v3,h3,l3);
                *(bf162*)(Ch + (size_t)r0 * N + col)       = bf162{h0,h1};
                *(bf162*)(Ch + (size_t)(r0 + 8) * N + col) = bf162{h2,h3};
                *(bf162*)(Cl + (size_t)r0 * N + col)       = bf162{l0,l1};
                *(bf162*)(Cl + (size_t)(r0 + 8) * N + col) = bf162{l2,l3};
            }
        }
    }
}

// ---------------- attention: scalar float4 math, 2 CTAs per (b,h) ----------------
// grid = BBATCH*HH*2, block = 256. Each CTA owns 256 query rows of one (b,h).
__global__ __launch_bounds__(256) void attn_kernel(const float* __restrict__ qkv,
                                                   bf16* __restrict__ ch,
                                                   bf16* __restrict__ cl) {
    const int bh = blockIdx.x >> 1;
    const int half = blockIdx.x & 1;
    const int b = bh / HH, h = bh % HH;
    __shared__ float4 Ks[SS][2];
    __shared__ float4 Vs[SS][2];
    const int t = threadIdx.x;         // 0..255
    const float* base = qkv + (size_t)b * SS * QKVN;

    // 256 threads load all 512 K/V rows (2 rows each)
#pragma unroll
    for (int rr = 0; rr < 2; rr++) {
        const int r = t + rr * 256;
        const float* kr = base + (size_t)r * QKVN + EE     + h * 8;
        const float* vr = base + (size_t)r * QKVN + 2 * EE + h * 8;
        Ks[r][0] = *(const float4*)kr;     Ks[r][1] = *(const float4*)(kr + 4);
        Vs[r][0] = *(const float4*)vr;     Vs[r][1] = *(const float4*)(vr + 4);
    }
    __syncthreads();

    const int qrow = half * 256 + t;
    const float sc = 0.35355339059327373f;   // 1/sqrt(8)
    float4 q0, q1;
    {
        const float* qr = base + (size_t)qrow * QKVN + h * 8;
        q0 = *(const float4*)qr; q1 = *(const float4*)(qr + 4);
        q0.x *= sc; q0.y *= sc; q0.z *= sc; q0.w *= sc;
        q1.x *= sc; q1.y *= sc; q1.z *= sc; q1.w *= sc;
    }

    float l = 0.f;
    float a0 = 0.f, a1 = 0.f, a2 = 0.f, a3 = 0.f;
    float a4 = 0.f, a5 = 0.f, a6 = 0.f, a7 = 0.f;
    for (int j = 0; j < SS; j++) {
        const float4 k0 = Ks[j][0], k1 = Ks[j][1];
        float s = q0.x * k0.x + q0.y * k0.y + q0.z * k0.z + q0.w * k0.w
                + q1.x * k1.x + q1.y * k1.y + q1.z * k1.z + q1.w * k1.w;
        const float p = __expf(s);          // scores bounded; no max-shift needed
        l += p;
        const float4 v0 = Vs[j][0], v1 = Vs[j][1];
        a0 += p * v0.x; a1 += p * v0.y; a2 += p * v0.z; a3 += p * v0.w;
        a4 += p * v1.x; a5 += p * v1.y; a6 += p * v1.z; a7 += p * v1.w;
    }
    const float inv = 1.f / l;
    const size_t o = (size_t)(b * SS + qrow) * EE + h * 8;
    float r[8] = { a0*inv, a1*inv, a2*inv, a3*inv, a4*inv, a5*inv, a6*inv, a7*inv };
    bf16 oh[8], ol[8];
#pragma unroll
    for (int d = 0; d < 8; d++) split1(r[d], oh[d], ol[d]);
    uint4 uh, ul;
    uh.x = pack2(oh[0],oh[1]); uh.y = pack2(oh[2],oh[3]);
    uh.z = pack2(oh[4],oh[5]); uh.w = pack2(oh[6],oh[7]);
    ul.x = pack2(ol[0],ol[1]); ul.y = pack2(ol[2],ol[3]);
    ul.z = pack2(ol[4],ol[5]); ul.w = pack2(ol[6],ol[7]);
    *(uint4*)(ch + o) = uh;
    *(uint4*)(cl + o) = ul;
}

// ---------------- fused residual add + layernorm over E=512 ----------------
template<bool SPLIT>
__global__ __launch_bounds__(128) void add_ln_kernel(const float* __restrict__ a,
                                                     const float* __restrict__ r,
                                                     const float* __restrict__ w,
                                                     const float* __restrict__ bb,
                                                     float* __restrict__ out,
                                                     bf16* __restrict__ oh,
                                                     bf16* __restrict__ ol) {
    const int row = blockIdx.x;
    const int t = threadIdx.x;
    const float4 av = ((const float4*)(a + (size_t)row * EE))[t];
    const float4 rv = ((const float4*)(r + (size_t)row * EE))[t];
    float v0 = av.x + rv.x, v1 = av.y + rv.y, v2 = av.z + rv.z, v3 = av.w + rv.w;

    __shared__ float sh[4];
    __shared__ float sh2[4];
    float s = v0 + v1 + v2 + v3;
#pragma unroll
    for (int o = 16; o; o >>= 1) s += __shfl_xor_sync(0xffffffffu, s, o);
    if ((t & 31) == 0) sh[t >> 5] = s;
    __syncthreads();
    const float mean = (sh[0] + sh[1] + sh[2] + sh[3]) * (1.f / 512.f);

    float d0 = v0 - mean, d1 = v1 - mean, d2 = v2 - mean, d3 = v3 - mean;
    float qsum = d0*d0 + d1*d1 + d2*d2 + d3*d3;
#pragma unroll
    for (int o = 16; o; o >>= 1) qsum += __shfl_xor_sync(0xffffffffu, qsum, o);
    if ((t & 31) == 0) sh2[t >> 5] = qsum;
    __syncthreads();
    const float var = (sh2[0] + sh2[1] + sh2[2] + sh2[3]) * (1.f / 512.f);
    const float inv = rsqrtf(var + 1e-5f);

    const float4 wv = ((const float4*)w)[t];
    const float4 bv = ((const float4*)bb)[t];
    float o0 = d0 * inv * wv.x + bv.x;
    float o1 = d1 * inv * wv.y + bv.y;
    float o2 = d2 * inv * wv.z + bv.z;
    float o3 = d3 * inv * wv.w + bv.w;
    ((float4*)(out + (size_t)row * EE))[t] = make_float4(o0, o1, o2, o3);
    if (SPLIT) {
        bf16 h0,h1,h2,h3,l0,l1,l2,l3;
        split1(o0,h0,l0); split1(o1,h1,l1); split1(o2,h2,l2); split1(o3,h3,l3);
        bf162* ph = (bf162*)(oh + (size_t)row * EE + t * 4);
        bf162* pl = (bf162*)(ol + (size_t)row * EE + t * 4);
        ph[0] = bf162{h0,h1}; ph[1] = bf162{h2,h3};
        pl[0] = bf162{l0,l1}; pl[1] = bf162{l2,l3};
    }
}

// ---------------- host launch ----------------
#define SMEMB(MFRAG) (3 * (2 * ((MFRAG)*32*80) + 2 * (128*80)))

extern "C" void kernel_launch(void* const* d_in, const int* in_sizes, int n_in,
                              void* d_out, int out_size) {
    const float* x     = (const float*)d_in[0];
    const float* in_w  = (const float*)d_in[1];
    const float* in_b  = (const float*)d_in[2];
    const float* out_w = (const float*)d_in[3];
    const float* out_b = (const float*)d_in[4];
    const float* ln1w  = (const float*)d_in[5];
    const float* ln1b  = (const float*)d_in[6];
    const float* ln2w  = (const float*)d_in[7];
    const float* ln2b  = (const float*)d_in[8];
    const float* w1    = (const float*)d_in[9];
    const float* b1    = (const float*)d_in[10];
    const float* w2    = (const float*)d_in[11];
    const float* b2    = (const float*)d_in[12];
    float* out = (float*)d_out;

    static bf16 *p_proj_h=nullptr, *p_proj_l, *p_ctx_h, *p_ctx_l,
                *p_x1h, *p_x1l, *p_hh, *p_hl, *p_wh, *p_wl;
    static float *p_qkv, *p_x1f, *p_t0;
    if (!p_proj_h) {
        cudaGetSymbolAddress((void**)&p_proj_h, g_proj_h);
        cudaGetSymbolAddress((void**)&p_proj_l, g_proj_l);
        cudaGetSymbolAddress((void**)&p_qkv,   g_qkv);
        cudaGetSymbolAddress((void**)&p_ctx_h, g_ctx_h);
        cudaGetSymbolAddress((void**)&p_ctx_l, g_ctx_l);
        cudaGetSymbolAddress((void**)&p_x1f,   g_x1f);
        cudaGetSymbolAddress((void**)&p_x1h,   g_x1_h);
        cudaGetSymbolAddress((void**)&p_x1l,   g_x1_l);
        cudaGetSymbolAddress((void**)&p_hh,    g_hh);
        cudaGetSymbolAddress((void**)&p_hl,    g_hl);
        cudaGetSymbolAddress((void**)&p_t0,    g_t0);
        cudaGetSymbolAddress((void**)&p_wh,    g_wh);
        cudaGetSymbolAddress((void**)&p_wl,    g_wl);
        cudaFuncSetAttribute(gemm_mma<4,0,false>, cudaFuncAttributeMaxDynamicSharedMemorySize, SMEMB(4));
        cudaFuncSetAttribute(gemm_mma<4,1,true >, cudaFuncAttributeMaxDynamicSharedMemorySize, SMEMB(4));
        cudaFuncSetAttribute(gemm_mma<2,0,false>, cudaFuncAttributeMaxDynamicSharedMemorySize, SMEMB(2));
    }

    // weight splits (one kernel)
    split_all_kernel<<<(W_TOTAL/4 + 255)/256, 256>>>(in_w, out_w, w1, w2, p_wh, p_wl);

    // proj (prefix-cos) with bf16 hi/lo split
    const int ngroups = MROWS * EE / 8;
    proj_kernel<<<(ngroups + 255)/256, 256>>>(x, p_proj_h, p_proj_l, ngroups);

    // qkv = proj @ in_w^T + in_b  (2048 x 1536, K=512) -> fp32
    gemm_mma<4,0,false><<<dim3(QKVN/128, MROWS/128), 256, SMEMB(4)>>>(
        p_proj_h, p_proj_l, p_wh + W_INW, p_wl + W_INW, in_b,
        p_qkv, nullptr, nullptr, QKVN, EE);

    // attention -> ctx hi/lo (2 CTAs per head)
    attn_kernel<<<BBATCH * HH * 2, 256>>>(p_qkv, p_ctx_h, p_ctx_l);

    // attn_out = ctx @ out_w^T + out_b (2048 x 512, K=512) -> t0 fp32 ; BM=64 grid=128
    gemm_mma<2,0,false><<<dim3(EE/128, MROWS/64), 256, SMEMB(2)>>>(
        p_ctx_h, p_ctx_l, p_wh + W_OUTW, p_wl + W_OUTW, out_b,
        p_t0, nullptr, nullptr, EE, EE);

    // x1 = LN(x + attn_out) -> fp32 + hi/lo
    add_ln_kernel<true><<<MROWS, 128>>>(x, p_t0, ln1w, ln1b, p_x1f, p_x1h, p_x1l);

    // h = relu(x1 @ w1^T + b1) (2048 x 2048, K=512) -> hi/lo only
    gemm_mma<4,1,true><<<dim3(FFNN/128, MROWS/128), 256, SMEMB(4)>>>(
        p_x1h, p_x1l, p_wh + W_W1, p_wl + W_W1, b1,
        nullptr, p_hh, p_hl, FFNN, EE);

    // ffn_out = h @ w2^T + b2 (2048 x 512, K=2048) -> t0 fp32 ; BM=64 grid=128
    gemm_mma<2,0,false><<<dim3(EE/128, MROWS/64), 256, SMEMB(2)>>>(
        p_hh, p_hl, p_wh + W_W2, p_wl + W_W2, b2,
        p_t0, nullptr, nullptr, EE, FFNN);

    // out = LN(x1 + ffn_out)
    add_ln_kernel<false><<<MROWS, 128>>>(p_x1f, p_t0, ln2w, ln2b, out, nullptr, nullptr);

    (void)in_sizes; (void)n_in; (void)out_size;
}

// round 12
// speedup vs baseline: 1.0143x; 1.0143x over previous
#include <cuda_runtime.h>
#include <cuda_bf16.h>
#include <math.h>
#include <stdint.h>

#define BBATCH 4
#define SS 512
#define EE 512
#define HH 64
#define FFNN 2048
#define MROWS 2048
#define QKVN 1536

typedef __nv_bfloat16 bf16;
typedef __nv_bfloat162 bf162;

// ---------------- scratch (__device__ globals; no allocations allowed) ----------------
__device__ bf16  g_proj_h[MROWS*EE];
__device__ bf16  g_proj_l[MROWS*EE];
__device__ float g_qkv  [MROWS*QKVN];
__device__ bf16  g_ctx_h[MROWS*EE];
__device__ bf16  g_ctx_l[MROWS*EE];
__device__ float g_x1f  [MROWS*EE];
__device__ bf16  g_x1_h [MROWS*EE];
__device__ bf16  g_x1_l [MROWS*EE];
__device__ bf16  g_hh   [MROWS*FFNN];
__device__ bf16  g_hl   [MROWS*FFNN];
__device__ float g_t0   [MROWS*EE];
#define W_INW  0
#define W_OUTW (QKVN*EE)
#define W_W1   (W_OUTW + EE*EE)
#define W_W2   (W_W1 + FFNN*EE)
#define W_TOTAL (W_W2 + EE*FFNN)
__device__ bf16  g_wh[W_TOTAL];
__device__ bf16  g_wl[W_TOTAL];

// ---------------- helpers ----------------
__device__ __forceinline__ void split1(float v, bf16& h, bf16& l) {
    h = __float2bfloat16(v);
    l = __float2bfloat16(v - __bfloat162float(h));
}
__device__ __forceinline__ uint32_t smem_u32(const void* p) {
    return (uint32_t)__cvta_generic_to_shared(p);
}
__device__ __forceinline__ void ldm_x4(uint32_t* r, uint32_t addr) {
    asm volatile("ldmatrix.sync.aligned.m8n8.x4.shared.b16 {%0,%1,%2,%3}, [%4];"
                 : "=r"(r[0]), "=r"(r[1]), "=r"(r[2]), "=r"(r[3]) : "r"(addr));
}
__device__ __forceinline__ void mma16816(float* c, const uint32_t* a, const uint32_t* b) {
    asm volatile("mma.sync.aligned.m16n8k16.row.col.f32.bf16.bf16.f32 "
                 "{%0,%1,%2,%3},{%4,%5,%6,%7},{%8,%9},{%0,%1,%2,%3};"
                 : "+f"(c[0]), "+f"(c[1]), "+f"(c[2]), "+f"(c[3])
                 : "r"(a[0]), "r"(a[1]), "r"(a[2]), "r"(a[3]), "r"(b[0]), "r"(b[1]));
}
__device__ __forceinline__ void cpa16(uint32_t dst, const void* src) {
    asm volatile("cp.async.cg.shared.global [%0], [%1], 16;" :: "r"(dst), "l"(src));
}
__device__ __forceinline__ uint32_t pack2(bf16 a, bf16 b) {
    bf162 t{a, b};
    return *reinterpret_cast<uint32_t*>(&t);
}

// ---------------- combined weight split ----------------
__global__ __launch_bounds__(256) void split_all_kernel(
    const float* __restrict__ in_w, const float* __restrict__ out_w,
    const float* __restrict__ w1, const float* __restrict__ w2,
    bf16* __restrict__ h, bf16* __restrict__ l) {
    int i = blockIdx.x * blockDim.x + threadIdx.x;   // float4 index
    if (i >= W_TOTAL / 4) return;
    int e = i * 4;
    const float* src; int off;
    if      (e < W_OUTW) { src = in_w;  off = e; }
    else if (e < W_W1)   { src = out_w; off = e - W_OUTW; }
    else if (e < W_W2)   { src = w1;    off = e - W_W1; }
    else                 { src = w2;    off = e - W_W2; }
    float4 v = *(const float4*)(src + off);
    bf16 h0,h1,h2,h3,l0,l1,l2,l3;
    split1(v.x,h0,l0); split1(v.y,h1,l1); split1(v.z,h2,l2); split1(v.w,h3,l3);
    ((bf162*)h)[i*2+0] = bf162{h0,h1};
    ((bf162*)h)[i*2+1] = bf162{h2,h3};
    ((bf162*)l)[i*2+0] = bf162{l0,l1};
    ((bf162*)l)[i*2+1] = bf162{l2,l3};
}

// ---------------- quantum projection == prefix product of cos ----------------
__global__ __launch_bounds__(256) void proj_kernel(const float* __restrict__ x,
                                                   bf16* __restrict__ ph,
                                                   bf16* __restrict__ pl, int ngroups) {
    int g = blockIdx.x * blockDim.x + threadIdx.x;
    if (g >= ngroups) return;
    const float4* xp = (const float4*)(x + (size_t)g * 8);
    float4 a = xp[0], b = xp[1];
    float r[8];
    r[0] = cosf(a.x);
    r[1] = r[0] * cosf(a.y);
    r[2] = r[1] * cosf(a.z);
    r[3] = r[2] * cosf(a.w);
    r[4] = r[3] * cosf(b.x);
    r[5] = r[4] * cosf(b.y);
    r[6] = r[5] * cosf(b.z);
    r[7] = r[6] * cosf(b.w);
    bf16 h[8], l[8];
#pragma unroll
    for (int i = 0; i < 8; i++) split1(r[i], h[i], l[i]);
    bf162* oh = (bf162*)(ph + (size_t)g * 8);
    bf162* ol = (bf162*)(pl + (size_t)g * 8);
#pragma unroll
    for (int i = 0; i < 4; i++) { oh[i] = bf162{h[2*i],h[2*i+1]}; ol[i] = bf162{l[2*i],l[2*i+1]}; }
}

// ---------------- 3xBF16 mma.sync GEMM: C = A(MxK) @ B(NxK)^T + bias ----------------
// BM = MFRAG*32, BN = 128, BK = 32, 4-stage cp.async pipeline, ONE barrier/iter.
template<int MFRAG, int EPI, bool RELU>
__global__ __launch_bounds__(256) void gemm_mma(
    const bf16* __restrict__ Ah, const bf16* __restrict__ Al,
    const bf16* __restrict__ Bh, const bf16* __restrict__ Bl,
    const float* __restrict__ bias,
    float* __restrict__ Cf, bf16* __restrict__ Ch, bf16* __restrict__ Cl,
    int N, int K)
{
    constexpr int BM = MFRAG * 32;
    constexpr int ROWB = 80;
    constexpr int A_SZ = BM * ROWB;
    constexpr int B_SZ = 128 * ROWB;
    constexpr int STAGE = 2 * A_SZ + 2 * B_SZ;

    extern __shared__ char dynsmem[];
    const uint32_t dbase = smem_u32(dynsmem);

    const int tid = threadIdx.x;
    const int lane = tid & 31, wid = tid >> 5;
    const int warp_m = wid >> 2, warp_n = wid & 3;
    const int m_base = warp_m * (MFRAG * 16);
    const int n_base = warp_n * 32;
    const int blockRow = blockIdx.y * BM;
    const int blockCol = blockIdx.x * 128;

    const int lg = lane >> 3, li = lane & 7;
    const int a_row = li + (lg & 1) * 8;
    const int a_col = (lg >> 1) * 8;
    const int b_row = li + (lg >> 1) * 8;
    const int b_col = (lg & 1) * 8;

    float acc[MFRAG][4][4];
#pragma unroll
    for (int mf = 0; mf < MFRAG; mf++)
#pragma unroll
        for (int nf = 0; nf < 4; nf++)
#pragma unroll
            for (int q = 0; q < 4; q++) acc[mf][nf][q] = 0.f;

    auto ld_arr = [&](const bf16* g, int row0, int k0, uint32_t sb, int rows) {
        const int nch = rows * 4;
        for (int c = tid; c < nch; c += 256) {
            int r = c >> 2, seg = c & 3;
            cpa16(sb + (uint32_t)(r * ROWB + seg * 16),
                  g + (size_t)(row0 + r) * K + k0 + seg * 8);
        }
    };
    auto load_chunk = [&](int s, int kt) {
        const uint32_t sb = dbase + (uint32_t)s * STAGE;
        const int k0 = kt * 32;
        ld_arr(Ah, blockRow, k0, sb, BM);
        ld_arr(Al, blockRow, k0, sb + A_SZ, BM);
        ld_arr(Bh, blockCol, k0, sb + 2 * A_SZ, 128);
        ld_arr(Bl, blockCol, k0, sb + 2 * A_SZ + B_SZ, 128);
        asm volatile("cp.async.commit_group;");
    };

    const int T = K / 32;            // >= 16
    load_chunk(0, 0);
    load_chunk(1, 1);
    load_chunk(2, 2);

    for (int it = 0; it < T; ++it) {
        if (it < T - 2)       asm volatile("cp.async.wait_group 2;");
        else if (it == T - 2) asm volatile("cp.async.wait_group 1;");
        else                  asm volatile("cp.async.wait_group 0;");
        __syncthreads();     // single barrier: orders prior-iter reads AND this chunk's arrival

        // refill the stage consumed LAST iteration ((it+3)%4): legal after the barrier
        if (it + 3 < T) load_chunk((it + 3) & 3, it + 3);

        const int s = it & 3;
        const uint32_t aH = dbase + (uint32_t)s * STAGE;
        const uint32_t aL = aH + A_SZ;
        const uint32_t bH = aH + 2 * A_SZ;
        const uint32_t bL = bH + B_SZ;

        uint32_t fah[2][MFRAG][4], fal[2][MFRAG][4], fbh[2][2][4], fbl[2][2][4];
#pragma unroll
        for (int j = 0; j < 2; j++) {
#pragma unroll
            for (int mf = 0; mf < MFRAG; mf++) {
                uint32_t ro = (uint32_t)((m_base + mf * 16 + a_row) * ROWB
                                         + (j * 16 + a_col) * 2);
                ldm_x4(fah[j][mf], aH + ro);
                ldm_x4(fal[j][mf], aL + ro);
            }
#pragma unroll
            for (int nt = 0; nt < 2; nt++) {
                uint32_t ro = (uint32_t)((n_base + nt * 16 + b_row) * ROWB
                                         + (j * 16 + b_col) * 2);
                ldm_x4(fbh[j][nt], bH + ro);
                ldm_x4(fbl[j][nt], bL + ro);
            }
        }
#pragma unroll
        for (int j = 0; j < 2; j++) {
#pragma unroll
            for (int mf = 0; mf < MFRAG; mf++) {
#pragma unroll
                for (int nt = 0; nt < 2; nt++) {
#pragma unroll
                    for (int h = 0; h < 2; h++) {
                        const int nf = nt * 2 + h;
                        uint32_t bh2[2] = { fbh[j][nt][2*h], fbh[j][nt][2*h+1] };
                        uint32_t bl2[2] = { fbl[j][nt][2*h], fbl[j][nt][2*h+1] };
                        mma16816(acc[mf][nf], fah[j][mf], bh2);
                        mma16816(acc[mf][nf], fah[j][mf], bl2);
                        mma16816(acc[mf][nf], fal[j][mf], bh2);
                    }
                }
            }
        }
    }

#pragma unroll
    for (int mf = 0; mf < MFRAG; mf++) {
        const int r0 = blockRow + m_base + mf * 16 + (lane >> 2);
#pragma unroll
        for (int nf = 0; nf < 4; nf++) {
            const int col = blockCol + n_base + nf * 8 + ((lane & 3) << 1);
            const float2 bv = *(const float2*)(bias + col);
            float v0 = acc[mf][nf][0] + bv.x;
            float v1 = acc[mf][nf][1] + bv.y;
            float v2 = acc[mf][nf][2] + bv.x;
            float v3 = acc[mf][nf][3] + bv.y;
            if (RELU) {
                v0 = fmaxf(v0, 0.f); v1 = fmaxf(v1, 0.f);
                v2 = fmaxf(v2, 0.f); v3 = fmaxf(v3, 0.f);
            }
            if (EPI == 0) {
                *(float2*)(Cf + (size_t)r0 * N + col)       = make_float2(v0, v1);
                *(float2*)(Cf + (size_t)(r0 + 8) * N + col) = make_float2(v2, v3);
            } else {
                bf16 h0,h1,h2,h3,l0,l1,l2,l3;
                split1(v0,h0,l0); split1(v1,h1,l1); split1(v2,h2,l2); split1(v3,h3,l3);
                *(bf162*)(Ch + (size_t)r0 * N + col)       = bf162{h0,h1};
                *(bf162*)(Ch + (size_t)(r0 + 8) * N + col) = bf162{h2,h3};
                *(bf162*)(Cl + (size_t)r0 * N + col)       = bf162{l0,l1};
                *(bf162*)(Cl + (size_t)(r0 + 8) * N + col) = bf162{l2,l3};
            }
        }
    }
}

// ---------------- attention: scalar float4 math, 2 CTAs per (b,h) ----------------
__global__ __launch_bounds__(256) void attn_kernel(const float* __restrict__ qkv,
                                                   bf16* __restrict__ ch,
                                                   bf16* __restrict__ cl) {
    const int bh = blockIdx.x >> 1;
    const int half = blockIdx.x & 1;
    const int b = bh / HH, h = bh % HH;
    __shared__ float4 Ks[SS][2];
    __shared__ float4 Vs[SS][2];
    const int t = threadIdx.x;
    const float* base = qkv + (size_t)b * SS * QKVN;

#pragma unroll
    for (int rr = 0; rr < 2; rr++) {
        const int r = t + rr * 256;
        const float* kr = base + (size_t)r * QKVN + EE     + h * 8;
        const float* vr = base + (size_t)r * QKVN + 2 * EE + h * 8;
        Ks[r][0] = *(const float4*)kr;     Ks[r][1] = *(const float4*)(kr + 4);
        Vs[r][0] = *(const float4*)vr;     Vs[r][1] = *(const float4*)(vr + 4);
    }
    __syncthreads();

    const int qrow = half * 256 + t;
    const float sc = 0.35355339059327373f;
    float4 q0, q1;
    {
        const float* qr = base + (size_t)qrow * QKVN + h * 8;
        q0 = *(const float4*)qr; q1 = *(const float4*)(qr + 4);
        q0.x *= sc; q0.y *= sc; q0.z *= sc; q0.w *= sc;
        q1.x *= sc; q1.y *= sc; q1.z *= sc; q1.w *= sc;
    }

    float l = 0.f;
    float a0 = 0.f, a1 = 0.f, a2 = 0.f, a3 = 0.f;
    float a4 = 0.f, a5 = 0.f, a6 = 0.f, a7 = 0.f;
    for (int j = 0; j < SS; j++) {
        const float4 k0 = Ks[j][0], k1 = Ks[j][1];
        float s = q0.x * k0.x + q0.y * k0.y + q0.z * k0.z + q0.w * k0.w
                + q1.x * k1.x + q1.y * k1.y + q1.z * k1.z + q1.w * k1.w;
        const float p = __expf(s);
        l += p;
        const float4 v0 = Vs[j][0], v1 = Vs[j][1];
        a0 += p * v0.x; a1 += p * v0.y; a2 += p * v0.z; a3 += p * v0.w;
        a4 += p * v1.x; a5 += p * v1.y; a6 += p * v1.z; a7 += p * v1.w;
    }
    const float inv = 1.f / l;
    const size_t o = (size_t)(b * SS + qrow) * EE + h * 8;
    float r[8] = { a0*inv, a1*inv, a2*inv, a3*inv, a4*inv, a5*inv, a6*inv, a7*inv };
    bf16 oh[8], ol[8];
#pragma unroll
    for (int d = 0; d < 8; d++) split1(r[d], oh[d], ol[d]);
    uint4 uh, ul;
    uh.x = pack2(oh[0],oh[1]); uh.y = pack2(oh[2],oh[3]);
    uh.z = pack2(oh[4],oh[5]); uh.w = pack2(oh[6],oh[7]);
    ul.x = pack2(ol[0],ol[1]); ul.y = pack2(ol[2],ol[3]);
    ul.z = pack2(ol[4],ol[5]); ul.w = pack2(ol[6],ol[7]);
    *(uint4*)(ch + o) = uh;
    *(uint4*)(cl + o) = ul;
}

// ---------------- fused residual add + layernorm over E=512 ----------------
template<bool SPLIT>
__global__ __launch_bounds__(128) void add_ln_kernel(const float* __restrict__ a,
                                                     const float* __restrict__ r,
                                                     const float* __restrict__ w,
                                                     const float* __restrict__ bb,
                                                     float* __restrict__ out,
                                                     bf16* __restrict__ oh,
                                                     bf16* __restrict__ ol) {
    const int row = blockIdx.x;
    const int t = threadIdx.x;
    const float4 av = ((const float4*)(a + (size_t)row * EE))[t];
    const float4 rv = ((const float4*)(r + (size_t)row * EE))[t];
    float v0 = av.x + rv.x, v1 = av.y + rv.y, v2 = av.z + rv.z, v3 = av.w + rv.w;

    __shared__ float sh[4];
    __shared__ float sh2[4];
    float s = v0 + v1 + v2 + v3;
#pragma unroll
    for (int o = 16; o; o >>= 1) s += __shfl_xor_sync(0xffffffffu, s, o);
    if ((t & 31) == 0) sh[t >> 5] = s;
    __syncthreads();
    const float mean = (sh[0] + sh[1] + sh[2] + sh[3]) * (1.f / 512.f);

    float d0 = v0 - mean, d1 = v1 - mean, d2 = v2 - mean, d3 = v3 - mean;
    float qsum = d0*d0 + d1*d1 + d2*d2 + d3*d3;
#pragma unroll
    for (int o = 16; o; o >>= 1) qsum += __shfl_xor_sync(0xffffffffu, qsum, o);
    if ((t & 31) == 0) sh2[t >> 5] = qsum;
    __syncthreads();
    const float var = (sh2[0] + sh2[1] + sh2[2] + sh2[3]) * (1.f / 512.f);
    const float inv = rsqrtf(var + 1e-5f);

    const float4 wv = ((const float4*)w)[t];
    const float4 bv = ((const float4*)bb)[t];
    float o0 = d0 * inv * wv.x + bv.x;
    float o1 = d1 * inv * wv.y + bv.y;
    float o2 = d2 * inv * wv.z + bv.z;
    float o3 = d3 * inv * wv.w + bv.w;
    ((float4*)(out + (size_t)row * EE))[t] = make_float4(o0, o1, o2, o3);
    if (SPLIT) {
        bf16 h0,h1,h2,h3,l0,l1,l2,l3;
        split1(o0,h0,l0); split1(o1,h1,l1); split1(o2,h2,l2); split1(o3,h3,l3);
        bf162* ph = (bf162*)(oh + (size_t)row * EE + t * 4);
        bf162* pl = (bf162*)(ol + (size_t)row * EE + t * 4);
        ph[0] = bf162{h0,h1}; ph[1] = bf162{h2,h3};
        pl[0] = bf162{l0,l1}; pl[1] = bf162{l2,l3};
    }
}

// ---------------- host launch ----------------
#define SMEMB(MFRAG) (4 * (2 * ((MFRAG)*32*80) + 2 * (128*80)))

extern "C" void kernel_launch(void* const* d_in, const int* in_sizes, int n_in,
                              void* d_out, int out_size) {
    const float* x     = (const float*)d_in[0];
    const float* in_w  = (const float*)d_in[1];
    const float* in_b  = (const float*)d_in[2];
    const float* out_w = (const float*)d_in[3];
    const float* out_b = (const float*)d_in[4];
    const float* ln1w  = (const float*)d_in[5];
    const float* ln1b  = (const float*)d_in[6];
    const float* ln2w  = (const float*)d_in[7];
    const float* ln2b  = (const float*)d_in[8];
    const float* w1    = (const float*)d_in[9];
    const float* b1    = (const float*)d_in[10];
    const float* w2    = (const float*)d_in[11];
    const float* b2    = (const float*)d_in[12];
    float* out = (float*)d_out;

    static bf16 *p_proj_h=nullptr, *p_proj_l, *p_ctx_h, *p_ctx_l,
                *p_x1h, *p_x1l, *p_hh, *p_hl, *p_wh, *p_wl;
    static float *p_qkv, *p_x1f, *p_t0;
    if (!p_proj_h) {
        cudaGetSymbolAddress((void**)&p_proj_h, g_proj_h);
        cudaGetSymbolAddress((void**)&p_proj_l, g_proj_l);
        cudaGetSymbolAddress((void**)&p_qkv,   g_qkv);
        cudaGetSymbolAddress((void**)&p_ctx_h, g_ctx_h);
        cudaGetSymbolAddress((void**)&p_ctx_l, g_ctx_l);
        cudaGetSymbolAddress((void**)&p_x1f,   g_x1f);
        cudaGetSymbolAddress((void**)&p_x1h,   g_x1_h);
        cudaGetSymbolAddress((void**)&p_x1l,   g_x1_l);
        cudaGetSymbolAddress((void**)&p_hh,    g_hh);
        cudaGetSymbolAddress((void**)&p_hl,    g_hl);
        cudaGetSymbolAddress((void**)&p_t0,    g_t0);
        cudaGetSymbolAddress((void**)&p_wh,    g_wh);
        cudaGetSymbolAddress((void**)&p_wl,    g_wl);
        cudaFuncSetAttribute(gemm_mma<4,0,false>, cudaFuncAttributeMaxDynamicSharedMemorySize, SMEMB(4));
        cudaFuncSetAttribute(gemm_mma<4,1,true >, cudaFuncAttributeMaxDynamicSharedMemorySize, SMEMB(4));
        cudaFuncSetAttribute(gemm_mma<2,0,false>, cudaFuncAttributeMaxDynamicSharedMemorySize, SMEMB(2));
    }

    // weight splits (one kernel)
    split_all_kernel<<<(W_TOTAL/4 + 255)/256, 256>>>(in_w, out_w, w1, w2, p_wh, p_wl);

    // proj (prefix-cos) with bf16 hi/lo split
    const int ngroups = MROWS * EE / 8;
    proj_kernel<<<(ngroups + 255)/256, 256>>>(x, p_proj_h, p_proj_l, ngroups);

    // qkv = proj @ in_w^T + in_b  (2048 x 1536, K=512) -> fp32 ; BM=64 grid=384
    gemm_mma<2,0,false><<<dim3(QKVN/128, MROWS/64), 256, SMEMB(2)>>>(
        p_proj_h, p_proj_l, p_wh + W_INW, p_wl + W_INW, in_b,
        p_qkv, nullptr, nullptr, QKVN, EE);

    // attention -> ctx hi/lo (2 CTAs per head)
    attn_kernel<<<BBATCH * HH * 2, 256>>>(p_qkv, p_ctx_h, p_ctx_l);

    // attn_out = ctx @ out_w^T + out_b (2048 x 512, K=512) -> t0 fp32 ; BM=64 grid=128
    gemm_mma<2,0,false><<<dim3(EE/128, MROWS/64), 256, SMEMB(2)>>>(
        p_ctx_h, p_ctx_l, p_wh + W_OUTW, p_wl + W_OUTW, out_b,
        p_t0, nullptr, nullptr, EE, EE);

    // x1 = LN(x + attn_out) -> fp32 + hi/lo
    add_ln_kernel<true><<<MROWS, 128>>>(x, p_t0, ln1w, ln1b, p_x1f, p_x1h, p_x1l);

    // h = relu(x1 @ w1^T + b1) (2048 x 2048, K=512) -> hi/lo only
    gemm_mma<4,1,true><<<dim3(FFNN/128, MROWS/128), 256, SMEMB(4)>>>(
        p_x1h, p_x1l, p_wh + W_W1, p_wl + W_W1, b1,
        nullptr, p_hh, p_hl, FFNN, EE);

    // ffn_out = h @ w2^T + b2 (2048 x 512, K=2048) -> t0 fp32 ; BM=64 grid=128
    gemm_mma<2,0,false><<<dim3(EE/128, MROWS/64), 256, SMEMB(2)>>>(
        p_hh, p_hl, p_wh + W_W2, p_wl + W_W2, b2,
        p_t0, nullptr, nullptr, EE, FFNN);

    // out = LN(x1 + ffn_out)
    add_ln_kernel<false><<<MROWS, 128>>>(p_x1f, p_t0, ln2w, ln2b, out, nullptr, nullptr);

    (void)in_sizes; (void)n_in; (void)out_size;
}

// round 13
// speedup vs baseline: 1.1934x; 1.1766x over previous
#include <cuda_runtime.h>
#include <cuda_bf16.h>
#include <math.h>
#include <stdint.h>

#define BBATCH 4
#define SS 512
#define EE 512
#define HH 64
#define FFNN 2048
#define MROWS 2048
#define QKVN 1536

typedef __nv_bfloat16 bf16;
typedef __nv_bfloat162 bf162;

// ---------------- padded-tile geometry ----------------
// Operand [R x K] bf16, tiled (TB rows x 32 cols) -> tile = TB*80 bytes
// element (r,k) byte = ((r/TB)*(K/32) + k/32)*TB*80 + (r%TB)*80 + (k%32)*2
#define TILE64  (64*80)    // 5120
#define TILE128 (128*80)   // 10240

// ---------------- scratch (__device__ globals; no allocations allowed) ----------------
__device__ __align__(1024) uint8_t g_pa_proj_h[32*16*TILE64];   // proj  TB=64 K=512
__device__ __align__(1024) uint8_t g_pa_proj_l[32*16*TILE64];
__device__ __align__(1024) uint8_t g_pa_ctx_h [32*16*TILE64];   // ctx   TB=64 K=512
__device__ __align__(1024) uint8_t g_pa_ctx_l [32*16*TILE64];
__device__ __align__(1024) uint8_t g_pa_x1_h  [16*16*TILE128];  // x1    TB=128 K=512
__device__ __align__(1024) uint8_t g_pa_x1_l  [16*16*TILE128];
__device__ __align__(1024) uint8_t g_pa_h_h   [32*64*TILE64];   // h     TB=64 K=2048
__device__ __align__(1024) uint8_t g_pa_h_l   [32*64*TILE64];
__device__ float g_qkv [MROWS*QKVN];
__device__ float g_x1f [MROWS*EE];
__device__ float g_t0  [MROWS*EE];
// padded weights, TB=128 (BN)
#define WPO_IN  0
#define WPO_OUT (12*16*TILE128)                 // 1,966,080
#define WPO_W1  (WPO_OUT + 4*16*TILE128)        // 2,621,440
#define WPO_W2  (WPO_W1 + 16*16*TILE128)        // 5,242,880
#define WP_TOTAL (WPO_W2 + 4*64*TILE128)        // 7,864,320
__device__ __align__(1024) uint8_t g_wp_h[WP_TOTAL];
__device__ __align__(1024) uint8_t g_wp_l[WP_TOTAL];

// ---------------- helpers ----------------
__device__ __forceinline__ void split1(float v, bf16& h, bf16& l) {
    h = __float2bfloat16(v);
    l = __float2bfloat16(v - __bfloat162float(h));
}
__device__ __forceinline__ uint32_t smem_u32(const void* p) {
    return (uint32_t)__cvta_generic_to_shared(p);
}
__device__ __forceinline__ void ldm_x4(uint32_t* r, uint32_t addr) {
    asm volatile("ldmatrix.sync.aligned.m8n8.x4.shared.b16 {%0,%1,%2,%3}, [%4];"
                 : "=r"(r[0]), "=r"(r[1]), "=r"(r[2]), "=r"(r[3]) : "r"(addr));
}
__device__ __forceinline__ void mma16816(float* c, const uint32_t* a, const uint32_t* b) {
    asm volatile("mma.sync.aligned.m16n8k16.row.col.f32.bf16.bf16.f32 "
                 "{%0,%1,%2,%3},{%4,%5,%6,%7},{%8,%9},{%0,%1,%2,%3};"
                 : "+f"(c[0]), "+f"(c[1]), "+f"(c[2]), "+f"(c[3])
                 : "r"(a[0]), "r"(a[1]), "r"(a[2]), "r"(a[3]), "r"(b[0]), "r"(b[1]));
}
__device__ __forceinline__ uint32_t pack2(bf16 a, bf16 b) {
    bf162 t{a, b};
    return *reinterpret_cast<uint32_t*>(&t);
}

#define MBAR_INIT(addr, cnt) \
    asm volatile("mbarrier.init.shared.b64 [%0], %1;" :: "r"(addr), "r"(cnt) : "memory")
#define MBAR_EXPECT_TX(addr, bytes) \
    asm volatile("mbarrier.arrive.expect_tx.shared.b64 _, [%0], %1;" :: "r"(addr), "r"(bytes) : "memory")
#define BULK_G2S(dst, src, bytes, mbar) \
    asm volatile("cp.async.bulk.shared::cta.global.mbarrier::complete_tx::bytes [%0], [%1], %2, [%3];" \
                 :: "r"(dst), "l"(src), "r"(bytes), "r"(mbar) : "memory")
#define MBAR_WAIT(addr, parity) do {                                             \
    uint32_t _m = (addr); uint32_t _p = (parity); uint32_t _done;                \
    asm volatile("{\n\t.reg .pred p;\n\t"                                        \
        "mbarrier.try_wait.parity.acquire.cta.shared::cta.b64 p, [%1], %2;\n\t"  \
        "selp.b32 %0, 1, 0, p;\n\t}" : "=r"(_done) : "r"(_m), "r"(_p) : "memory");\
    if (!_done) {                                                                \
        asm volatile("{\n\t.reg .pred P1;\n\t"                                   \
            "WL_%=:\n\t"                                                         \
            "mbarrier.try_wait.parity.acquire.cta.shared::cta.b64 P1, [%0], %1, 0x989680;\n\t" \
            "@P1 bra.uni WD_%=;\n\t"                                             \
            "bra.uni WL_%=;\n\t"                                                 \
            "WD_%=:\n\t}" :: "r"(_m), "r"(_p) : "memory");                       \
    }                                                                            \
} while (0)

// ---------------- combined weight split -> padded tiles (TB=128) ----------------
#define W_OUTW (QKVN*EE)
#define W_W1   (W_OUTW + EE*EE)
#define W_W2   (W_W1 + FFNN*EE)
#define W_TOTAL (W_W2 + EE*FFNN)
__global__ __launch_bounds__(256) void split_all_kernel(
    const float* __restrict__ in_w, const float* __restrict__ out_w,
    const float* __restrict__ w1, const float* __restrict__ w2,
    uint8_t* __restrict__ hp, uint8_t* __restrict__ lp) {
    int i = blockIdx.x * blockDim.x + threadIdx.x;   // float4 index
    if (i >= W_TOTAL / 4) return;
    int e = i * 4;
    const float* src; int off; int Km, nkc; size_t wpo;
    if      (e < W_OUTW) { src = in_w;  off = e;          Km = 512;  nkc = 16; wpo = WPO_IN; }
    else if (e < W_W1)   { src = out_w; off = e - W_OUTW; Km = 512;  nkc = 16; wpo = WPO_OUT; }
    else if (e < W_W2)   { src = w1;    off = e - W_W1;   Km = 512;  nkc = 16; wpo = WPO_W1; }
    else                 { src = w2;    off = e - W_W2;   Km = 2048; nkc = 64; wpo = WPO_W2; }
    int n = off / Km, k = off % Km;
    float4 v = *(const float4*)(src + off);
    bf16 h0,h1,h2,h3,l0,l1,l2,l3;
    split1(v.x,h0,l0); split1(v.y,h1,l1); split1(v.z,h2,l2); split1(v.w,h3,l3);
    size_t byte = wpo + ((size_t)(n >> 7) * nkc + (k >> 5)) * TILE128
                + (size_t)(n & 127) * 80 + (k & 31) * 2;
    uint2 uh, ul;
    uh.x = pack2(h0,h1); uh.y = pack2(h2,h3);
    ul.x = pack2(l0,l1); ul.y = pack2(l2,l3);
    *(uint2*)(hp + byte) = uh;
    *(uint2*)(lp + byte) = ul;
}

// ---------------- quantum projection == prefix product of cos -> padded (TB=64,K=512) ----------------
__global__ __launch_bounds__(256) void proj_kernel(const float* __restrict__ x,
                                                   uint8_t* __restrict__ ph,
                                                   uint8_t* __restrict__ pl, int ngroups) {
    int g = blockIdx.x * blockDim.x + threadIdx.x;
    if (g >= ngroups) return;
    const float4* xp = (const float4*)(x + (size_t)g * 8);
    float4 a = xp[0], b = xp[1];
    float r[8];
    r[0] = cosf(a.x);
    r[1] = r[0] * cosf(a.y);
    r[2] = r[1] * cosf(a.z);
    r[3] = r[2] * cosf(a.w);
    r[4] = r[3] * cosf(b.x);
    r[5] = r[4] * cosf(b.y);
    r[6] = r[5] * cosf(b.z);
    r[7] = r[6] * cosf(b.w);
    bf16 h[8], l[8];
#pragma unroll
    for (int i = 0; i < 8; i++) split1(r[i], h[i], l[i]);
    const int row = g >> 6;                 // 64 groups per row (512/8)
    const int k0  = (g & 63) * 8;
    size_t byte = ((size_t)(row >> 6) * 16 + (k0 >> 5)) * TILE64
                + (size_t)(row & 63) * 80 + (k0 & 31) * 2;
    uint4 uh, ul;
    uh.x = pack2(h[0],h[1]); uh.y = pack2(h[2],h[3]);
    uh.z = pack2(h[4],h[5]); uh.w = pack2(h[6],h[7]);
    ul.x = pack2(l[0],l[1]); ul.y = pack2(l[2],l[3]);
    ul.z = pack2(l[4],l[5]); ul.w = pack2(l[6],l[7]);
    *(uint4*)(ph + byte) = uh;
    *(uint4*)(pl + byte) = ul;
}

// ---------------- 3xBF16 mma.sync GEMM, bulk-copy pipeline ----------------
// A/B operands pre-tiled in global (A: TB=BM, B: TB=128). 4 stages, mbarrier per stage.
// EPI: 0 -> fp32 linear out; 1 -> bf16 hi/lo PADDED out (TB=64, K_out = N).
template<int MFRAG, int EPI, bool RELU>
__global__ __launch_bounds__(256) void gemm_mma(
    const uint8_t* __restrict__ Aph, const uint8_t* __restrict__ Apl,
    const uint8_t* __restrict__ Bph, const uint8_t* __restrict__ Bpl,
    const float* __restrict__ bias,
    float* __restrict__ Cf, uint8_t* __restrict__ Chp, uint8_t* __restrict__ Clp,
    int N, int K)
{
    constexpr int BM = MFRAG * 32;
    constexpr int ROWB = 80;
    constexpr uint32_t A_SZ = BM * ROWB;          // == A tile bytes
    constexpr uint32_t B_SZ = 128 * ROWB;         // == B tile bytes
    constexpr uint32_t STAGE = 2 * A_SZ + 2 * B_SZ;

    extern __shared__ char dynsmem[];
    const uint32_t hdr = smem_u32(dynsmem);       // 4 mbarriers @ hdr+0,8,16,24
    const uint32_t dbase = hdr + 1024;

    const int tid = threadIdx.x;
    const int lane = tid & 31, wid = tid >> 5;
    const int warp_m = wid >> 2, warp_n = wid & 3;
    const int m_base = warp_m * (MFRAG * 16);
    const int n_base = warp_n * 32;
    const int blockRow = blockIdx.y * BM;
    const int blockCol = blockIdx.x * 128;
    const int T = K / 32;

    const int lg = lane >> 3, li = lane & 7;
    const int a_row = li + (lg & 1) * 8;
    const int a_col = (lg >> 1) * 8;
    const int b_row = li + (lg >> 1) * 8;
    const int b_col = (lg & 1) * 8;

    float acc[MFRAG][4][4];
#pragma unroll
    for (int mf = 0; mf < MFRAG; mf++)
#pragma unroll
        for (int nf = 0; nf < 4; nf++)
#pragma unroll
            for (int q = 0; q < 4; q++) acc[mf][nf][q] = 0.f;

    auto issue = [&](int s, int kt) {
        const uint32_t mb = hdr + (uint32_t)s * 8;
        MBAR_EXPECT_TX(mb, STAGE);
        const uint32_t sb = dbase + (uint32_t)s * STAGE;
        const uint8_t* ab = Aph + ((size_t)blockIdx.y * T + kt) * A_SZ;
        const uint8_t* al = Apl + ((size_t)blockIdx.y * T + kt) * A_SZ;
        const uint8_t* bb = Bph + ((size_t)blockIdx.x * T + kt) * B_SZ;
        const uint8_t* bl = Bpl + ((size_t)blockIdx.x * T + kt) * B_SZ;
        BULK_G2S(sb,                ab, A_SZ, mb);
        BULK_G2S(sb + A_SZ,         al, A_SZ, mb);
        BULK_G2S(sb + 2*A_SZ,       bb, B_SZ, mb);
        BULK_G2S(sb + 2*A_SZ+B_SZ,  bl, B_SZ, mb);
    };

    if (tid == 0) {
        MBAR_INIT(hdr + 0, 1u);
        MBAR_INIT(hdr + 8, 1u);
        MBAR_INIT(hdr + 16, 1u);
        MBAR_INIT(hdr + 24, 1u);
    }
    __syncthreads();
    if (tid == 0) { issue(0, 0); issue(1, 1); issue(2, 2); }

    for (int it = 0; it < T; ++it) {
        __syncthreads();                           // all done reading stage (it-1)&3
        if (tid == 0 && it + 3 < T) issue((it + 3) & 3, it + 3);

        const int s = it & 3;
        MBAR_WAIT(hdr + (uint32_t)s * 8, (uint32_t)((it >> 2) & 1));

        const uint32_t aH = dbase + (uint32_t)s * STAGE;
        const uint32_t aL = aH + A_SZ;
        const uint32_t bH = aH + 2 * A_SZ;
        const uint32_t bL = bH + B_SZ;

        uint32_t fah[2][MFRAG][4], fal[2][MFRAG][4], fbh[2][2][4], fbl[2][2][4];
#pragma unroll
        for (int j = 0; j < 2; j++) {
#pragma unroll
            for (int mf = 0; mf < MFRAG; mf++) {
                uint32_t ro = (uint32_t)((m_base + mf * 16 + a_row) * ROWB
                                         + (j * 16 + a_col) * 2);
                ldm_x4(fah[j][mf], aH + ro);
                ldm_x4(fal[j][mf], aL + ro);
            }
#pragma unroll
            for (int nt = 0; nt < 2; nt++) {
                uint32_t ro = (uint32_t)((n_base + nt * 16 + b_row) * ROWB
                                         + (j * 16 + b_col) * 2);
                ldm_x4(fbh[j][nt], bH + ro);
                ldm_x4(fbl[j][nt], bL + ro);
            }
        }
#pragma unroll
        for (int j = 0; j < 2; j++) {
#pragma unroll
            for (int mf = 0; mf < MFRAG; mf++) {
#pragma unroll
                for (int nt = 0; nt < 2; nt++) {
#pragma unroll
                    for (int h = 0; h < 2; h++) {
                        const int nf = nt * 2 + h;
                        uint32_t bh2[2] = { fbh[j][nt][2*h], fbh[j][nt][2*h+1] };
                        uint32_t bl2[2] = { fbl[j][nt][2*h], fbl[j][nt][2*h+1] };
                        mma16816(acc[mf][nf], fah[j][mf], bh2);
                        mma16816(acc[mf][nf], fah[j][mf], bl2);
                        mma16816(acc[mf][nf], fal[j][mf], bh2);
                    }
                }
            }
        }
    }

#pragma unroll
    for (int mf = 0; mf < MFRAG; mf++) {
        const int r0 = blockRow + m_base + mf * 16 + (lane >> 2);
#pragma unroll
        for (int nf = 0; nf < 4; nf++) {
            const int col = blockCol + n_base + nf * 8 + ((lane & 3) << 1);
            const float2 bv = *(const float2*)(bias + col);
            float v0 = acc[mf][nf][0] + bv.x;
            float v1 = acc[mf][nf][1] + bv.y;
            float v2 = acc[mf][nf][2] + bv.x;
            float v3 = acc[mf][nf][3] + bv.y;
            if (RELU) {
                v0 = fmaxf(v0, 0.f); v1 = fmaxf(v1, 0.f);
                v2 = fmaxf(v2, 0.f); v3 = fmaxf(v3, 0.f);
            }
            if (EPI == 0) {
                *(float2*)(Cf + (size_t)r0 * N + col)       = make_float2(v0, v1);
                *(float2*)(Cf + (size_t)(r0 + 8) * N + col) = make_float2(v2, v3);
            } else {
                // padded out: TB=64, K_out = N (nkc = N/32)
                bf16 h0,h1,h2,h3,l0,l1,l2,l3;
                split1(v0,h0,l0); split1(v1,h1,l1); split1(v2,h2,l2); split1(v3,h3,l3);
                const int nkc = N >> 5;
                size_t by0 = ((size_t)(r0 >> 6) * nkc + (col >> 5)) * TILE64
                           + (size_t)(r0 & 63) * 80 + (col & 31) * 2;
                const int r1 = r0 + 8;
                size_t by1 = ((size_t)(r1 >> 6) * nkc + (col >> 5)) * TILE64
                           + (size_t)(r1 & 63) * 80 + (col & 31) * 2;
                *(uint32_t*)(Chp + by0) = pack2(h0,h1);
                *(uint32_t*)(Chp + by1) = pack2(h2,h3);
                *(uint32_t*)(Clp + by0) = pack2(l0,l1);
                *(uint32_t*)(Clp + by1) = pack2(l2,l3);
            }
        }
    }
}

// ---------------- attention: scalar float4 math, 2 CTAs per (b,h); ctx -> padded (TB=64) ----------------
__global__ __launch_bounds__(256) void attn_kernel(const float* __restrict__ qkv,
                                                   uint8_t* __restrict__ chp,
                                                   uint8_t* __restrict__ clp) {
    const int bh = blockIdx.x >> 1;
    const int half = blockIdx.x & 1;
    const int b = bh / HH, h = bh % HH;
    __shared__ float4 Ks[SS][2];
    __shared__ float4 Vs[SS][2];
    const int t = threadIdx.x;
    const float* base = qkv + (size_t)b * SS * QKVN;

#pragma unroll
    for (int rr = 0; rr < 2; rr++) {
        const int r = t + rr * 256;
        const float* kr = base + (size_t)r * QKVN + EE     + h * 8;
        const float* vr = base + (size_t)r * QKVN + 2 * EE + h * 8;
        Ks[r][0] = *(const float4*)kr;     Ks[r][1] = *(const float4*)(kr + 4);
        Vs[r][0] = *(const float4*)vr;     Vs[r][1] = *(const float4*)(vr + 4);
    }
    __syncthreads();

    const int qrow = half * 256 + t;
    const float sc = 0.35355339059327373f;
    float4 q0, q1;
    {
        const float* qr = base + (size_t)qrow * QKVN + h * 8;
        q0 = *(const float4*)qr; q1 = *(const float4*)(qr + 4);
        q0.x *= sc; q0.y *= sc; q0.z *= sc; q0.w *= sc;
        q1.x *= sc; q1.y *= sc; q1.z *= sc; q1.w *= sc;
    }

    float l = 0.f;
    float a0 = 0.f, a1 = 0.f, a2 = 0.f, a3 = 0.f;
    float a4 = 0.f, a5 = 0.f, a6 = 0.f, a7 = 0.f;
    for (int j = 0; j < SS; j++) {
        const float4 k0 = Ks[j][0], k1 = Ks[j][1];
        float s = q0.x * k0.x + q0.y * k0.y + q0.z * k0.z + q0.w * k0.w
                + q1.x * k1.x + q1.y * k1.y + q1.z * k1.z + q1.w * k1.w;
        const float p = __expf(s);
        l += p;
        const float4 v0 = Vs[j][0], v1 = Vs[j][1];
        a0 += p * v0.x; a1 += p * v0.y; a2 += p * v0.z; a3 += p * v0.w;
        a4 += p * v1.x; a5 += p * v1.y; a6 += p * v1.z; a7 += p * v1.w;
    }
    const float inv = 1.f / l;
    float r[8] = { a0*inv, a1*inv, a2*inv, a3*inv, a4*inv, a5*inv, a6*inv, a7*inv };
    bf16 oh[8], ol[8];
#pragma unroll
    for (int d = 0; d < 8; d++) split1(r[d], oh[d], ol[d]);
    const int row = b * SS + qrow;
    const int k0 = h * 8;
    size_t byte = ((size_t)(row >> 6) * 16 + (k0 >> 5)) * TILE64
                + (size_t)(row & 63) * 80 + (k0 & 31) * 2;
    uint4 uh, ul;
    uh.x = pack2(oh[0],oh[1]); uh.y = pack2(oh[2],oh[3]);
    uh.z = pack2(oh[4],oh[5]); uh.w = pack2(oh[6],oh[7]);
    ul.x = pack2(ol[0],ol[1]); ul.y = pack2(ol[2],ol[3]);
    ul.z = pack2(ol[4],ol[5]); ul.w = pack2(ol[6],ol[7]);
    *(uint4*)(chp + byte) = uh;
    *(uint4*)(clp + byte) = ul;
}

// ---------------- fused residual add + layernorm; SPLIT -> padded (TB=128, K=512) ----------------
template<bool SPLIT>
__global__ __launch_bounds__(128) void add_ln_kernel(const float* __restrict__ a,
                                                     const float* __restrict__ r,
                                                     const float* __restrict__ w,
                                                     const float* __restrict__ bb,
                                                     float* __restrict__ out,
                                                     uint8_t* __restrict__ ohp,
                                                     uint8_t* __restrict__ olp) {
    const int row = blockIdx.x;
    const int t = threadIdx.x;
    const float4 av = ((const float4*)(a + (size_t)row * EE))[t];
    const float4 rv = ((const float4*)(r + (size_t)row * EE))[t];
    float v0 = av.x + rv.x, v1 = av.y + rv.y, v2 = av.z + rv.z, v3 = av.w + rv.w;

    __shared__ float sh[4];
    __shared__ float sh2[4];
    float s = v0 + v1 + v2 + v3;
#pragma unroll
    for (int o = 16; o; o >>= 1) s += __shfl_xor_sync(0xffffffffu, s, o);
    if ((t & 31) == 0) sh[t >> 5] = s;
    __syncthreads();
    const float mean = (sh[0] + sh[1] + sh[2] + sh[3]) * (1.f / 512.f);

    float d0 = v0 - mean, d1 = v1 - mean, d2 = v2 - mean, d3 = v3 - mean;
    float qsum = d0*d0 + d1*d1 + d2*d2 + d3*d3;
#pragma unroll
    for (int o = 16; o; o >>= 1) qsum += __shfl_xor_sync(0xffffffffu, qsum, o);
    if ((t & 31) == 0) sh2[t >> 5] = qsum;
    __syncthreads();
    const float var = (sh2[0] + sh2[1] + sh2[2] + sh2[3]) * (1.f / 512.f);
    const float inv = rsqrtf(var + 1e-5f);

    const float4 wv = ((const float4*)w)[t];
    const float4 bv = ((const float4*)bb)[t];
    float o0 = d0 * inv * wv.x + bv.x;
    float o1 = d1 * inv * wv.y + bv.y;
    float o2 = d2 * inv * wv.z + bv.z;
    float o3 = d3 * inv * wv.w + bv.w;
    ((float4*)(out + (size_t)row * EE))[t] = make_float4(o0, o1, o2, o3);
    if (SPLIT) {
        bf16 h0,h1,h2,h3,l0,l1,l2,l3;
        split1(o0,h0,l0); split1(o1,h1,l1); split1(o2,h2,l2); split1(o3,h3,l3);
        const int k0 = t * 4;
        size_t byte = ((size_t)(row >> 7) * 16 + (k0 >> 5)) * TILE128
                    + (size_t)(row & 127) * 80 + (k0 & 31) * 2;
        uint2 uh, ul;
        uh.x = pack2(h0,h1); uh.y = pack2(h2,h3);
        ul.x = pack2(l0,l1); ul.y = pack2(l2,l3);
        *(uint2*)(ohp + byte) = uh;
        *(uint2*)(olp + byte) = ul;
    }
}

// ---------------- host launch ----------------
#define SMEMB(MFRAG) (1024 + 4 * (2 * ((MFRAG)*32*80) + 2 * (128*80)))

extern "C" void kernel_launch(void* const* d_in, const int* in_sizes, int n_in,
                              void* d_out, int out_size) {
    const float* x     = (const float*)d_in[0];
    const float* in_w  = (const float*)d_in[1];
    const float* in_b  = (const float*)d_in[2];
    const float* out_w = (const float*)d_in[3];
    const float* out_b = (const float*)d_in[4];
    const float* ln1w  = (const float*)d_in[5];
    const float* ln1b  = (const float*)d_in[6];
    const float* ln2w  = (const float*)d_in[7];
    const float* ln2b  = (const float*)d_in[8];
    const float* w1    = (const float*)d_in[9];
    const float* b1    = (const float*)d_in[10];
    const float* w2    = (const float*)d_in[11];
    const float* b2    = (const float*)d_in[12];
    float* out = (float*)d_out;

    static uint8_t *pp_h=nullptr, *pp_l, *pc_h, *pc_l, *px_h, *px_l, *ph_h, *ph_l, *pw_h, *pw_l;
    static float *p_qkv, *p_x1f, *p_t0;
    if (!pp_h) {
        cudaGetSymbolAddress((void**)&pp_h, g_pa_proj_h);
        cudaGetSymbolAddress((void**)&pp_l, g_pa_proj_l);
        cudaGetSymbolAddress((void**)&pc_h, g_pa_ctx_h);
        cudaGetSymbolAddress((void**)&pc_l, g_pa_ctx_l);
        cudaGetSymbolAddress((void**)&px_h, g_pa_x1_h);
        cudaGetSymbolAddress((void**)&px_l, g_pa_x1_l);
        cudaGetSymbolAddress((void**)&ph_h, g_pa_h_h);
        cudaGetSymbolAddress((void**)&ph_l, g_pa_h_l);
        cudaGetSymbolAddress((void**)&pw_h, g_wp_h);
        cudaGetSymbolAddress((void**)&pw_l, g_wp_l);
        cudaGetSymbolAddress((void**)&p_qkv, g_qkv);
        cudaGetSymbolAddress((void**)&p_x1f, g_x1f);
        cudaGetSymbolAddress((void**)&p_t0,  g_t0);
        cudaFuncSetAttribute(gemm_mma<4,1,true >, cudaFuncAttributeMaxDynamicSharedMemorySize, SMEMB(4));
        cudaFuncSetAttribute(gemm_mma<2,0,false>, cudaFuncAttributeMaxDynamicSharedMemorySize, SMEMB(2));
    }

    // weight splits -> padded tiles
    split_all_kernel<<<(W_TOTAL/4 + 255)/256, 256>>>(in_w, out_w, w1, w2, pw_h, pw_l);

    // proj -> padded tiles (TB=64)
    const int ngroups = MROWS * EE / 8;
    proj_kernel<<<(ngroups + 255)/256, 256>>>(x, pp_h, pp_l, ngroups);

    // qkv = proj @ in_w^T + in_b  (2048 x 1536, K=512) -> fp32 linear ; BM=64 grid=384
    gemm_mma<2,0,false><<<dim3(QKVN/128, MROWS/64), 256, SMEMB(2)>>>(
        pp_h, pp_l, pw_h + WPO_IN, pw_l + WPO_IN, in_b,
        p_qkv, nullptr, nullptr, QKVN, EE);

    // attention -> ctx padded (TB=64)
    attn_kernel<<<BBATCH * HH * 2, 256>>>(p_qkv, pc_h, pc_l);

    // attn_out = ctx @ out_w^T + out_b (2048 x 512, K=512) -> t0 fp32 ; BM=64 grid=128
    gemm_mma<2,0,false><<<dim3(EE/128, MROWS/64), 256, SMEMB(2)>>>(
        pc_h, pc_l, pw_h + WPO_OUT, pw_l + WPO_OUT, out_b,
        p_t0, nullptr, nullptr, EE, EE);

    // x1 = LN(x + attn_out) -> fp32 + padded hi/lo (TB=128)
    add_ln_kernel<true><<<MROWS, 128>>>(x, p_t0, ln1w, ln1b, p_x1f, px_h, px_l);

    // h = relu(x1 @ w1^T + b1) (2048 x 2048, K=512) -> padded hi/lo (TB=64, K_out=2048)
    gemm_mma<4,1,true><<<dim3(FFNN/128, MROWS/128), 256, SMEMB(4)>>>(
        px_h, px_l, pw_h + WPO_W1, pw_l + WPO_W1, b1,
        nullptr, ph_h, ph_l, FFNN, EE);

    // ffn_out = h @ w2^T + b2 (2048 x 512, K=2048) -> t0 fp32 ; BM=64 grid=128
    gemm_mma<2,0,false><<<dim3(EE/128, MROWS/64), 256, SMEMB(2)>>>(
        ph_h, ph_l, pw_h + WPO_W2, pw_l + WPO_W2, b2,
        p_t0, nullptr, nullptr, EE, FFNN);

    // out = LN(x1 + ffn_out)
    add_ln_kernel<false><<<MROWS, 128>>>(p_x1f, p_t0, ln2w, ln2b, out, nullptr, nullptr);

    (void)in_sizes; (void)n_in; (void)out_size;
}

// round 14
// speedup vs baseline: 1.2441x; 1.0424x over previous
#include <cuda_runtime.h>
#include <cuda_bf16.h>
#include <math.h>
#include <stdint.h>

#define BBATCH 4
#define SS 512
#define EE 512
#define HH 64
#define FFNN 2048
#define MROWS 2048
#define QKVN 1536

typedef __nv_bfloat16 bf16;
typedef __nv_bfloat162 bf162;

// ---------------- padded-tile geometry ----------------
// Operand [R x K] bf16, tiled (TB rows x 32 cols) -> tile = TB*80 bytes
#define TILE64  (64*80)    // 5120
#define TILE128 (128*80)   // 10240

// ---------------- scratch ----------------
__device__ __align__(1024) uint8_t g_pa_proj_h[32*16*TILE64];   // proj TB=64 K=512
__device__ __align__(1024) uint8_t g_pa_proj_l[32*16*TILE64];
__device__ __align__(1024) uint8_t g_pa_ctx_h [32*16*TILE64];   // ctx  TB=64 K=512
__device__ __align__(1024) uint8_t g_pa_ctx_l [32*16*TILE64];
__device__ __align__(1024) uint8_t g_pa_x1_h  [32*16*TILE64];   // x1   TB=64 K=512
__device__ __align__(1024) uint8_t g_pa_x1_l  [32*16*TILE64];
__device__ __align__(1024) uint8_t g_pa_h_h   [32*64*TILE64];   // h    TB=64 K=2048
__device__ __align__(1024) uint8_t g_pa_h_l   [32*64*TILE64];
__device__ float g_qkv [MROWS*QKVN];
__device__ float g_x1f [MROWS*EE];
__device__ float g_t0  [MROWS*EE];
// padded weights, TB=128 (BN)
#define WPO_IN  0
#define WPO_OUT (12*16*TILE128)
#define WPO_W1  (WPO_OUT + 4*16*TILE128)
#define WPO_W2  (WPO_W1 + 16*16*TILE128)
#define WP_TOTAL (WPO_W2 + 4*64*TILE128)
__device__ __align__(1024) uint8_t g_wp_h[WP_TOTAL];
__device__ __align__(1024) uint8_t g_wp_l[WP_TOTAL];

// ---------------- helpers ----------------
__device__ __forceinline__ void split1(float v, bf16& h, bf16& l) {
    h = __float2bfloat16(v);
    l = __float2bfloat16(v - __bfloat162float(h));
}
__device__ __forceinline__ uint32_t smem_u32(const void* p) {
    return (uint32_t)__cvta_generic_to_shared(p);
}
__device__ __forceinline__ void ldm_x4(uint32_t* r, uint32_t addr) {
    asm volatile("ldmatrix.sync.aligned.m8n8.x4.shared.b16 {%0,%1,%2,%3}, [%4];"
                 : "=r"(r[0]), "=r"(r[1]), "=r"(r[2]), "=r"(r[3]) : "r"(addr));
}
__device__ __forceinline__ void mma16816(float* c, const uint32_t* a, const uint32_t* b) {
    asm volatile("mma.sync.aligned.m16n8k16.row.col.f32.bf16.bf16.f32 "
                 "{%0,%1,%2,%3},{%4,%5,%6,%7},{%8,%9},{%0,%1,%2,%3};"
                 : "+f"(c[0]), "+f"(c[1]), "+f"(c[2]), "+f"(c[3])
                 : "r"(a[0]), "r"(a[1]), "r"(a[2]), "r"(a[3]), "r"(b[0]), "r"(b[1]));
}
__device__ __forceinline__ uint32_t pack2(bf16 a, bf16 b) {
    bf162 t{a, b};
    return *reinterpret_cast<uint32_t*>(&t);
}

#define MBAR_INIT(addr, cnt) \
    asm volatile("mbarrier.init.shared.b64 [%0], %1;" :: "r"(addr), "r"(cnt) : "memory")
#define MBAR_EXPECT_TX(addr, bytes) \
    asm volatile("mbarrier.arrive.expect_tx.shared.b64 _, [%0], %1;" :: "r"(addr), "r"(bytes) : "memory")
#define BULK_G2S(dst, src, bytes, mbar) \
    asm volatile("cp.async.bulk.shared::cta.global.mbarrier::complete_tx::bytes [%0], [%1], %2, [%3];" \
                 :: "r"(dst), "l"(src), "r"(bytes), "r"(mbar) : "memory")
#define MBAR_WAIT(addr, parity) do {                                             \
    uint32_t _m = (addr); uint32_t _p = (parity); uint32_t _done;                \
    asm volatile("{\n\t.reg .pred p;\n\t"                                        \
        "mbarrier.try_wait.parity.acquire.cta.shared::cta.b64 p, [%1], %2;\n\t"  \
        "selp.b32 %0, 1, 0, p;\n\t}" : "=r"(_done) : "r"(_m), "r"(_p) : "memory");\
    if (!_done) {                                                                \
        asm volatile("{\n\t.reg .pred P1;\n\t"                                   \
            "WL_%=:\n\t"                                                         \
            "mbarrier.try_wait.parity.acquire.cta.shared::cta.b64 P1, [%0], %1, 0x989680;\n\t" \
            "@P1 bra.uni WD_%=;\n\t"                                             \
            "bra.uni WL_%=;\n\t"                                                 \
            "WD_%=:\n\t}" :: "r"(_m), "r"(_p) : "memory");                       \
    }                                                                            \
} while (0)

// ---------------- combined weight split -> padded tiles (TB=128) ----------------
#define W_OUTW (QKVN*EE)
#define W_W1   (W_OUTW + EE*EE)
#define W_W2   (W_W1 + FFNN*EE)
#define W_TOTAL (W_W2 + EE*FFNN)
__global__ __launch_bounds__(256) void split_all_kernel(
    const float* __restrict__ in_w, const float* __restrict__ out_w,
    const float* __restrict__ w1, const float* __restrict__ w2,
    uint8_t* __restrict__ hp, uint8_t* __restrict__ lp) {
    int i = blockIdx.x * blockDim.x + threadIdx.x;
    if (i >= W_TOTAL / 4) return;
    int e = i * 4;
    const float* src; int off; int Km, nkc; size_t wpo;
    if      (e < W_OUTW) { src = in_w;  off = e;          Km = 512;  nkc = 16; wpo = WPO_IN; }
    else if (e < W_W1)   { src = out_w; off = e - W_OUTW; Km = 512;  nkc = 16; wpo = WPO_OUT; }
    else if (e < W_W2)   { src = w1;    off = e - W_W1;   Km = 512;  nkc = 16; wpo = WPO_W1; }
    else                 { src = w2;    off = e - W_W2;   Km = 2048; nkc = 64; wpo = WPO_W2; }
    int n = off / Km, k = off % Km;
    float4 v = *(const float4*)(src + off);
    bf16 h0,h1,h2,h3,l0,l1,l2,l3;
    split1(v.x,h0,l0); split1(v.y,h1,l1); split1(v.z,h2,l2); split1(v.w,h3,l3);
    size_t byte = wpo + ((size_t)(n >> 7) * nkc + (k >> 5)) * TILE128
                + (size_t)(n & 127) * 80 + (k & 31) * 2;
    uint2 uh, ul;
    uh.x = pack2(h0,h1); uh.y = pack2(h2,h3);
    ul.x = pack2(l0,l1); ul.y = pack2(l2,l3);
    *(uint2*)(hp + byte) = uh;
    *(uint2*)(lp + byte) = ul;
}

// ---------------- quantum projection -> padded (TB=64,K=512) ----------------
__global__ __launch_bounds__(256) void proj_kernel(const float* __restrict__ x,
                                                   uint8_t* __restrict__ ph,
                                                   uint8_t* __restrict__ pl, int ngroups) {
    int g = blockIdx.x * blockDim.x + threadIdx.x;
    if (g >= ngroups) return;
    const float4* xp = (const float4*)(x + (size_t)g * 8);
    float4 a = xp[0], b = xp[1];
    float r[8];
    r[0] = cosf(a.x);
    r[1] = r[0] * cosf(a.y);
    r[2] = r[1] * cosf(a.z);
    r[3] = r[2] * cosf(a.w);
    r[4] = r[3] * cosf(b.x);
    r[5] = r[4] * cosf(b.y);
    r[6] = r[5] * cosf(b.z);
    r[7] = r[6] * cosf(b.w);
    bf16 h[8], l[8];
#pragma unroll
    for (int i = 0; i < 8; i++) split1(r[i], h[i], l[i]);
    const int row = g >> 6;
    const int k0  = (g & 63) * 8;
    size_t byte = ((size_t)(row >> 6) * 16 + (k0 >> 5)) * TILE64
                + (size_t)(row & 63) * 80 + (k0 & 31) * 2;
    uint4 uh, ul;
    uh.x = pack2(h[0],h[1]); uh.y = pack2(h[2],h[3]);
    uh.z = pack2(h[4],h[5]); uh.w = pack2(h[6],h[7]);
    ul.x = pack2(l[0],l[1]); ul.y = pack2(l[2],l[3]);
    ul.z = pack2(l[4],l[5]); ul.w = pack2(l[6],l[7]);
    *(uint4*)(ph + byte) = uh;
    *(uint4*)(pl + byte) = ul;
}

// ---------------- 3xBF16 mma.sync GEMM, bulk-copy, 3 stages, BM=64 (2 CTAs/SM) ----------------
// EPI: 0 -> fp32 linear out; 1 -> bf16 hi/lo PADDED out (TB=64, K_out = N).
template<int EPI, bool RELU>
__global__ __launch_bounds__(256) void gemm_mma(
    const uint8_t* __restrict__ Aph, const uint8_t* __restrict__ Apl,
    const uint8_t* __restrict__ Bph, const uint8_t* __restrict__ Bpl,
    const float* __restrict__ bias,
    float* __restrict__ Cf, uint8_t* __restrict__ Chp, uint8_t* __restrict__ Clp,
    int N, int K)
{
    constexpr int MFRAG = 2, BM = 64;
    constexpr int ROWB = 80;
    constexpr uint32_t A_SZ = BM * ROWB;          // 5120
    constexpr uint32_t B_SZ = 128 * ROWB;         // 10240
    constexpr uint32_t STAGE = 2 * A_SZ + 2 * B_SZ;   // 30720

    extern __shared__ char dynsmem[];
    const uint32_t hdr = smem_u32(dynsmem);       // 3 mbarriers
    const uint32_t dbase = hdr + 1024;

    const int tid = threadIdx.x;
    const int lane = tid & 31, wid = tid >> 5;
    const int warp_m = wid >> 2, warp_n = wid & 3;
    const int m_base = warp_m * (MFRAG * 16);
    const int n_base = warp_n * 32;
    const int blockRow = blockIdx.y * BM;
    const int blockCol = blockIdx.x * 128;
    const int T = K / 32;

    const int lg = lane >> 3, li = lane & 7;
    const int a_row = li + (lg & 1) * 8;
    const int a_col = (lg >> 1) * 8;
    const int b_row = li + (lg >> 1) * 8;
    const int b_col = (lg & 1) * 8;

    float acc[MFRAG][4][4];
#pragma unroll
    for (int mf = 0; mf < MFRAG; mf++)
#pragma unroll
        for (int nf = 0; nf < 4; nf++)
#pragma unroll
            for (int q = 0; q < 4; q++) acc[mf][nf][q] = 0.f;

    auto issue = [&](int s, int kt) {
        const uint32_t mb = hdr + (uint32_t)s * 8;
        MBAR_EXPECT_TX(mb, STAGE);
        const uint32_t sb = dbase + (uint32_t)s * STAGE;
        const uint8_t* ab = Aph + ((size_t)blockIdx.y * T + kt) * A_SZ;
        const uint8_t* al = Apl + ((size_t)blockIdx.y * T + kt) * A_SZ;
        const uint8_t* bb = Bph + ((size_t)blockIdx.x * T + kt) * B_SZ;
        const uint8_t* bl = Bpl + ((size_t)blockIdx.x * T + kt) * B_SZ;
        BULK_G2S(sb,                ab, A_SZ, mb);
        BULK_G2S(sb + A_SZ,         al, A_SZ, mb);
        BULK_G2S(sb + 2*A_SZ,       bb, B_SZ, mb);
        BULK_G2S(sb + 2*A_SZ+B_SZ,  bl, B_SZ, mb);
    };

    if (tid == 0) {
        MBAR_INIT(hdr + 0, 1u);
        MBAR_INIT(hdr + 8, 1u);
        MBAR_INIT(hdr + 16, 1u);
    }
    __syncthreads();
    if (tid == 0) { issue(0, 0); issue(1, 1); }

    for (int it = 0; it < T; ++it) {
        __syncthreads();                          // everyone done reading stage (it-1)%3
        if (tid == 0 && it + 2 < T) issue((it + 2) % 3, it + 2);

        const int s = it % 3;
        MBAR_WAIT(hdr + (uint32_t)s * 8, (uint32_t)((it / 3) & 1));

        const uint32_t aH = dbase + (uint32_t)s * STAGE;
        const uint32_t aL = aH + A_SZ;
        const uint32_t bH = aH + 2 * A_SZ;
        const uint32_t bL = bH + B_SZ;

        uint32_t fah[2][MFRAG][4], fal[2][MFRAG][4], fbh[2][2][4], fbl[2][2][4];
#pragma unroll
        for (int j = 0; j < 2; j++) {
#pragma unroll
            for (int mf = 0; mf < MFRAG; mf++) {
                uint32_t ro = (uint32_t)((m_base + mf * 16 + a_row) * ROWB
                                         + (j * 16 + a_col) * 2);
                ldm_x4(fah[j][mf], aH + ro);
                ldm_x4(fal[j][mf], aL + ro);
            }
#pragma unroll
            for (int nt = 0; nt < 2; nt++) {
                uint32_t ro = (uint32_t)((n_base + nt * 16 + b_row) * ROWB
                                         + (j * 16 + b_col) * 2);
                ldm_x4(fbh[j][nt], bH + ro);
                ldm_x4(fbl[j][nt], bL + ro);
            }
        }
#pragma unroll
        for (int j = 0; j < 2; j++) {
#pragma unroll
            for (int mf = 0; mf < MFRAG; mf++) {
#pragma unroll
                for (int nt = 0; nt < 2; nt++) {
#pragma unroll
                    for (int h = 0; h < 2; h++) {
                        const int nf = nt * 2 + h;
                        uint32_t bh2[2] = { fbh[j][nt][2*h], fbh[j][nt][2*h+1] };
                        uint32_t bl2[2] = { fbl[j][nt][2*h], fbl[j][nt][2*h+1] };
                        mma16816(acc[mf][nf], fah[j][mf], bh2);
                        mma16816(acc[mf][nf], fah[j][mf], bl2);
                        mma16816(acc[mf][nf], fal[j][mf], bh2);
                    }
                }
            }
        }
    }

#pragma unroll
    for (int mf = 0; mf < MFRAG; mf++) {
        const int r0 = blockRow + m_base + mf * 16 + (lane >> 2);
#pragma unroll
        for (int nf = 0; nf < 4; nf++) {
            const int col = blockCol + n_base + nf * 8 + ((lane & 3) << 1);
            const float2 bv = *(const float2*)(bias + col);
            float v0 = acc[mf][nf][0] + bv.x;
            float v1 = acc[mf][nf][1] + bv.y;
            float v2 = acc[mf][nf][2] + bv.x;
            float v3 = acc[mf][nf][3] + bv.y;
            if (RELU) {
                v0 = fmaxf(v0, 0.f); v1 = fmaxf(v1, 0.f);
                v2 = fmaxf(v2, 0.f); v3 = fmaxf(v3, 0.f);
            }
            if (EPI == 0) {
                *(float2*)(Cf + (size_t)r0 * N + col)       = make_float2(v0, v1);
                *(float2*)(Cf + (size_t)(r0 + 8) * N + col) = make_float2(v2, v3);
            } else {
                bf16 h0,h1,h2,h3,l0,l1,l2,l3;
                split1(v0,h0,l0); split1(v1,h1,l1); split1(v2,h2,l2); split1(v3,h3,l3);
                const int nkc = N >> 5;
                size_t by0 = ((size_t)(r0 >> 6) * nkc + (col >> 5)) * TILE64
                           + (size_t)(r0 & 63) * 80 + (col & 31) * 2;
                const int r1 = r0 + 8;
                size_t by1 = ((size_t)(r1 >> 6) * nkc + (col >> 5)) * TILE64
                           + (size_t)(r1 & 63) * 80 + (col & 31) * 2;
                *(uint32_t*)(Chp + by0) = pack2(h0,h1);
                *(uint32_t*)(Chp + by1) = pack2(h2,h3);
                *(uint32_t*)(Clp + by0) = pack2(l0,l1);
                *(uint32_t*)(Clp + by1) = pack2(l2,l3);
            }
        }
    }
}

// ---------------- attention: scalar float4 math, 2 CTAs per (b,h); ctx -> padded (TB=64) ----------------
__global__ __launch_bounds__(256) void attn_kernel(const float* __restrict__ qkv,
                                                   uint8_t* __restrict__ chp,
                                                   uint8_t* __restrict__ clp) {
    const int bh = blockIdx.x >> 1;
    const int half = blockIdx.x & 1;
    const int b = bh / HH, h = bh % HH;
    __shared__ float4 Ks[SS][2];
    __shared__ float4 Vs[SS][2];
    const int t = threadIdx.x;
    const float* base = qkv + (size_t)b * SS * QKVN;

#pragma unroll
    for (int rr = 0; rr < 2; rr++) {
        const int r = t + rr * 256;
        const float* kr = base + (size_t)r * QKVN + EE     + h * 8;
        const float* vr = base + (size_t)r * QKVN + 2 * EE + h * 8;
        Ks[r][0] = *(const float4*)kr;     Ks[r][1] = *(const float4*)(kr + 4);
        Vs[r][0] = *(const float4*)vr;     Vs[r][1] = *(const float4*)(vr + 4);
    }
    __syncthreads();

    const int qrow = half * 256 + t;
    const float sc = 0.35355339059327373f;
    float4 q0, q1;
    {
        const float* qr = base + (size_t)qrow * QKVN + h * 8;
        q0 = *(const float4*)qr; q1 = *(const float4*)(qr + 4);
        q0.x *= sc; q0.y *= sc; q0.z *= sc; q0.w *= sc;
        q1.x *= sc; q1.y *= sc; q1.z *= sc; q1.w *= sc;
    }

    float l = 0.f;
    float a0 = 0.f, a1 = 0.f, a2 = 0.f, a3 = 0.f;
    float a4 = 0.f, a5 = 0.f, a6 = 0.f, a7 = 0.f;
    for (int j = 0; j < SS; j++) {
        const float4 k0 = Ks[j][0], k1 = Ks[j][1];
        float s = q0.x * k0.x + q0.y * k0.y + q0.z * k0.z + q0.w * k0.w
                + q1.x * k1.x + q1.y * k1.y + q1.z * k1.z + q1.w * k1.w;
        const float p = __expf(s);
        l += p;
        const float4 v0 = Vs[j][0], v1 = Vs[j][1];
        a0 += p * v0.x; a1 += p * v0.y; a2 += p * v0.z; a3 += p * v0.w;
        a4 += p * v1.x; a5 += p * v1.y; a6 += p * v1.z; a7 += p * v1.w;
    }
    const float inv = 1.f / l;
    float r[8] = { a0*inv, a1*inv, a2*inv, a3*inv, a4*inv, a5*inv, a6*inv, a7*inv };
    bf16 oh[8], ol[8];
#pragma unroll
    for (int d = 0; d < 8; d++) split1(r[d], oh[d], ol[d]);
    const int row = b * SS + qrow;
    const int k0 = h * 8;
    size_t byte = ((size_t)(row >> 6) * 16 + (k0 >> 5)) * TILE64
                + (size_t)(row & 63) * 80 + (k0 & 31) * 2;
    uint4 uh, ul;
    uh.x = pack2(oh[0],oh[1]); uh.y = pack2(oh[2],oh[3]);
    uh.z = pack2(oh[4],oh[5]); uh.w = pack2(oh[6],oh[7]);
    ul.x = pack2(ol[0],ol[1]); ul.y = pack2(ol[2],ol[3]);
    ul.z = pack2(ol[4],ol[5]); ul.w = pack2(ol[6],ol[7]);
    *(uint4*)(chp + byte) = uh;
    *(uint4*)(clp + byte) = ul;
}

// ---------------- fused residual add + layernorm; SPLIT -> padded (TB=64, K=512) ----------------
template<bool SPLIT>
__global__ __launch_bounds__(128) void add_ln_kernel(const float* __restrict__ a,
                                                     const float* __restrict__ r,
                                                     const float* __restrict__ w,
                                                     const float* __restrict__ bb,
                                                     float* __restrict__ out,
                                                     uint8_t* __restrict__ ohp,
                                                     uint8_t* __restrict__ olp) {
    const int row = blockIdx.x;
    const int t = threadIdx.x;
    const float4 av = ((const float4*)(a + (size_t)row * EE))[t];
    const float4 rv = ((const float4*)(r + (size_t)row * EE))[t];
    float v0 = av.x + rv.x, v1 = av.y + rv.y, v2 = av.z + rv.z, v3 = av.w + rv.w;

    __shared__ float sh[4];
    __shared__ float sh2[4];
    float s = v0 + v1 + v2 + v3;
#pragma unroll
    for (int o = 16; o; o >>= 1) s += __shfl_xor_sync(0xffffffffu, s, o);
    if ((t & 31) == 0) sh[t >> 5] = s;
    __syncthreads();
    const float mean = (sh[0] + sh[1] + sh[2] + sh[3]) * (1.f / 512.f);

    float d0 = v0 - mean, d1 = v1 - mean, d2 = v2 - mean, d3 = v3 - mean;
    float qsum = d0*d0 + d1*d1 + d2*d2 + d3*d3;
#pragma unroll
    for (int o = 16; o; o >>= 1) qsum += __shfl_xor_sync(0xffffffffu, qsum, o);
    if ((t & 31) == 0) sh2[t >> 5] = qsum;
    __syncthreads();
    const float var = (sh2[0] + sh2[1] + sh2[2] + sh2[3]) * (1.f / 512.f);
    const float inv = rsqrtf(var + 1e-5f);

    const float4 wv = ((const float4*)w)[t];
    const float4 bv = ((const float4*)bb)[t];
    float o0 = d0 * inv * wv.x + bv.x;
    float o1 = d1 * inv * wv.y + bv.y;
    float o2 = d2 * inv * wv.z + bv.z;
    float o3 = d3 * inv * wv.w + bv.w;
    ((float4*)(out + (size_t)row * EE))[t] = make_float4(o0, o1, o2, o3);
    if (SPLIT) {
        bf16 h0,h1,h2,h3,l0,l1,l2,l3;
        split1(o0,h0,l0); split1(o1,h1,l1); split1(o2,h2,l2); split1(o3,h3,l3);
        const int k0 = t * 4;
        size_t byte = ((size_t)(row >> 6) * 16 + (k0 >> 5)) * TILE64
                    + (size_t)(row & 63) * 80 + (k0 & 31) * 2;
        uint2 uh, ul;
        uh.x = pack2(h0,h1); uh.y = pack2(h2,h3);
        ul.x = pack2(l0,l1); ul.y = pack2(l2,l3);
        *(uint2*)(ohp + byte) = uh;
        *(uint2*)(olp + byte) = ul;
    }
}

// ---------------- host launch ----------------
#define SMEMB (1024 + 3 * (2 * (64*80) + 2 * (128*80)))   // 93184

extern "C" void kernel_launch(void* const* d_in, const int* in_sizes, int n_in,
                              void* d_out, int out_size) {
    const float* x     = (const float*)d_in[0];
    const float* in_w  = (const float*)d_in[1];
    const float* in_b  = (const float*)d_in[2];
    const float* out_w = (const float*)d_in[3];
    const float* out_b = (const float*)d_in[4];
    const float* ln1w  = (const float*)d_in[5];
    const float* ln1b  = (const float*)d_in[6];
    const float* ln2w  = (const float*)d_in[7];
    const float* ln2b  = (const float*)d_in[8];
    const float* w1    = (const float*)d_in[9];
    const float* b1    = (const float*)d_in[10];
    const float* w2    = (const float*)d_in[11];
    const float* b2    = (const float*)d_in[12];
    float* out = (float*)d_out;

    static uint8_t *pp_h=nullptr, *pp_l, *pc_h, *pc_l, *px_h, *px_l, *ph_h, *ph_l, *pw_h, *pw_l;
    static float *p_qkv, *p_x1f, *p_t0;
    if (!pp_h) {
        cudaGetSymbolAddress((void**)&pp_h, g_pa_proj_h);
        cudaGetSymbolAddress((void**)&pp_l, g_pa_proj_l);
        cudaGetSymbolAddress((void**)&pc_h, g_pa_ctx_h);
        cudaGetSymbolAddress((void**)&pc_l, g_pa_ctx_l);
        cudaGetSymbolAddress((void**)&px_h, g_pa_x1_h);
        cudaGetSymbolAddress((void**)&px_l, g_pa_x1_l);
        cudaGetSymbolAddress((void**)&ph_h, g_pa_h_h);
        cudaGetSymbolAddress((void**)&ph_l, g_pa_h_l);
        cudaGetSymbolAddress((void**)&pw_h, g_wp_h);
        cudaGetSymbolAddress((void**)&pw_l, g_wp_l);
        cudaGetSymbolAddress((void**)&p_qkv, g_qkv);
        cudaGetSymbolAddress((void**)&p_x1f, g_x1f);
        cudaGetSymbolAddress((void**)&p_t0,  g_t0);
        cudaFuncSetAttribute(gemm_mma<0,false>, cudaFuncAttributeMaxDynamicSharedMemorySize, SMEMB);
        cudaFuncSetAttribute(gemm_mma<1,true >, cudaFuncAttributeMaxDynamicSharedMemorySize, SMEMB);
    }

    // weight splits -> padded tiles
    split_all_kernel<<<(W_TOTAL/4 + 255)/256, 256>>>(in_w, out_w, w1, w2, pw_h, pw_l);

    // proj -> padded tiles (TB=64)
    const int ngroups = MROWS * EE / 8;
    proj_kernel<<<(ngroups + 255)/256, 256>>>(x, pp_h, pp_l, ngroups);

    // qkv = proj @ in_w^T + in_b  (2048 x 1536, K=512) -> fp32 linear ; grid 12x32
    gemm_mma<0,false><<<dim3(QKVN/128, MROWS/64), 256, SMEMB>>>(
        pp_h, pp_l, pw_h + WPO_IN, pw_l + WPO_IN, in_b,
        p_qkv, nullptr, nullptr, QKVN, EE);

    // attention -> ctx padded (TB=64)
    attn_kernel<<<BBATCH * HH * 2, 256>>>(p_qkv, pc_h, pc_l);

    // attn_out = ctx @ out_w^T + out_b (2048 x 512, K=512) -> t0 fp32 ; grid 4x32
    gemm_mma<0,false><<<dim3(EE/128, MROWS/64), 256, SMEMB>>>(
        pc_h, pc_l, pw_h + WPO_OUT, pw_l + WPO_OUT, out_b,
        p_t0, nullptr, nullptr, EE, EE);

    // x1 = LN(x + attn_out) -> fp32 + padded hi/lo (TB=64)
    add_ln_kernel<true><<<MROWS, 128>>>(x, p_t0, ln1w, ln1b, p_x1f, px_h, px_l);

    // h = relu(x1 @ w1^T + b1) (2048 x 2048, K=512) -> padded hi/lo (TB=64, K_out=2048) ; grid 16x32
    gemm_mma<1,true><<<dim3(FFNN/128, MROWS/64), 256, SMEMB>>>(
        px_h, px_l, pw_h + WPO_W1, pw_l + WPO_W1, b1,
        nullptr, ph_h, ph_l, FFNN, EE);

    // ffn_out = h @ w2^T + b2 (2048 x 512, K=2048) -> t0 fp32 ; grid 4x32
    gemm_mma<0,false><<<dim3(EE/128, MROWS/64), 256, SMEMB>>>(
        ph_h, ph_l, pw_h + WPO_W2, pw_l + WPO_W2, b2,
        p_t0, nullptr, nullptr, EE, FFNN);

    // out = LN(x1 + ffn_out)
    add_ln_kernel<false><<<MROWS, 128>>>(p_x1f, p_t0, ln2w, ln2b, out, nullptr, nullptr);

    (void)in_sizes; (void)n_in; (void)out_size;
}

// round 15
// speedup vs baseline: 1.2924x; 1.0388x over previous
#include <cuda_runtime.h>
#include <cuda_bf16.h>
#include <math.h>
#include <stdint.h>

#define BBATCH 4
#define SS 512
#define EE 512
#define HH 64
#define FFNN 2048
#define MROWS 2048
#define QKVN 1536
#define KSPLIT 4
#define KCH (SS / KSPLIT)          // 128 keys per CTA

typedef __nv_bfloat16 bf16;
typedef __nv_bfloat162 bf162;

// ---------------- padded-tile geometry ----------------
#define TILE64  (64*80)
#define TILE128 (128*80)

// ---------------- scratch ----------------
__device__ __align__(1024) uint8_t g_pa_proj_h[32*16*TILE64];
__device__ __align__(1024) uint8_t g_pa_proj_l[32*16*TILE64];
__device__ __align__(1024) uint8_t g_pa_ctx_h [32*16*TILE64];
__device__ __align__(1024) uint8_t g_pa_ctx_l [32*16*TILE64];
__device__ __align__(1024) uint8_t g_pa_x1_h  [32*16*TILE64];
__device__ __align__(1024) uint8_t g_pa_x1_l  [32*16*TILE64];
__device__ __align__(1024) uint8_t g_pa_h_h   [32*64*TILE64];
__device__ __align__(1024) uint8_t g_pa_h_l   [32*64*TILE64];
__device__ float g_qkv [MROWS*QKVN];
__device__ float g_x1f [MROWS*EE];
__device__ float g_t0  [MROWS*EE];
__device__ float g_pl  [BBATCH*HH*KSPLIT*SS];        // partial l
__device__ float g_pacc[BBATCH*HH*KSPLIT*SS*8];      // partial acc
#define WPO_IN  0
#define WPO_OUT (12*16*TILE128)
#define WPO_W1  (WPO_OUT + 4*16*TILE128)
#define WPO_W2  (WPO_W1 + 16*16*TILE128)
#define WP_TOTAL (WPO_W2 + 4*64*TILE128)
__device__ __align__(1024) uint8_t g_wp_h[WP_TOTAL];
__device__ __align__(1024) uint8_t g_wp_l[WP_TOTAL];

// ---------------- helpers ----------------
__device__ __forceinline__ void split1(float v, bf16& h, bf16& l) {
    h = __float2bfloat16(v);
    l = __float2bfloat16(v - __bfloat162float(h));
}
__device__ __forceinline__ uint32_t smem_u32(const void* p) {
    return (uint32_t)__cvta_generic_to_shared(p);
}
__device__ __forceinline__ void ldm_x4(uint32_t* r, uint32_t addr) {
    asm volatile("ldmatrix.sync.aligned.m8n8.x4.shared.b16 {%0,%1,%2,%3}, [%4];"
                 : "=r"(r[0]), "=r"(r[1]), "=r"(r[2]), "=r"(r[3]) : "r"(addr));
}
__device__ __forceinline__ void mma16816(float* c, const uint32_t* a, const uint32_t* b) {
    asm volatile("mma.sync.aligned.m16n8k16.row.col.f32.bf16.bf16.f32 "
                 "{%0,%1,%2,%3},{%4,%5,%6,%7},{%8,%9},{%0,%1,%2,%3};"
                 : "+f"(c[0]), "+f"(c[1]), "+f"(c[2]), "+f"(c[3])
                 : "r"(a[0]), "r"(a[1]), "r"(a[2]), "r"(a[3]), "r"(b[0]), "r"(b[1]));
}
__device__ __forceinline__ uint32_t pack2(bf16 a, bf16 b) {
    bf162 t{a, b};
    return *reinterpret_cast<uint32_t*>(&t);
}

#define MBAR_INIT(addr, cnt) \
    asm volatile("mbarrier.init.shared.b64 [%0], %1;" :: "r"(addr), "r"(cnt) : "memory")
#define MBAR_EXPECT_TX(addr, bytes) \
    asm volatile("mbarrier.arrive.expect_tx.shared.b64 _, [%0], %1;" :: "r"(addr), "r"(bytes) : "memory")
#define BULK_G2S(dst, src, bytes, mbar) \
    asm volatile("cp.async.bulk.shared::cta.global.mbarrier::complete_tx::bytes [%0], [%1], %2, [%3];" \
                 :: "r"(dst), "l"(src), "r"(bytes), "r"(mbar) : "memory")
#define MBAR_WAIT(addr, parity) do {                                             \
    uint32_t _m = (addr); uint32_t _p = (parity); uint32_t _done;                \
    asm volatile("{\n\t.reg .pred p;\n\t"                                        \
        "mbarrier.try_wait.parity.acquire.cta.shared::cta.b64 p, [%1], %2;\n\t"  \
        "selp.b32 %0, 1, 0, p;\n\t}" : "=r"(_done) : "r"(_m), "r"(_p) : "memory");\
    if (!_done) {                                                                \
        asm volatile("{\n\t.reg .pred P1;\n\t"                                   \
            "WL_%=:\n\t"                                                         \
            "mbarrier.try_wait.parity.acquire.cta.shared::cta.b64 P1, [%0], %1, 0x989680;\n\t" \
            "@P1 bra.uni WD_%=;\n\t"                                             \
            "bra.uni WL_%=;\n\t"                                                 \
            "WD_%=:\n\t}" :: "r"(_m), "r"(_p) : "memory");                       \
    }                                                                            \
} while (0)

// ---------------- combined weight split -> padded tiles (TB=128) ----------------
#define W_OUTW (QKVN*EE)
#define W_W1   (W_OUTW + EE*EE)
#define W_W2   (W_W1 + FFNN*EE)
#define W_TOTAL (W_W2 + EE*FFNN)
__global__ __launch_bounds__(256) void split_all_kernel(
    const float* __restrict__ in_w, const float* __restrict__ out_w,
    const float* __restrict__ w1, const float* __restrict__ w2,
    uint8_t* __restrict__ hp, uint8_t* __restrict__ lp) {
    int i = blockIdx.x * blockDim.x + threadIdx.x;
    if (i >= W_TOTAL / 4) return;
    int e = i * 4;
    const float* src; int off; int Km, nkc; size_t wpo;
    if      (e < W_OUTW) { src = in_w;  off = e;          Km = 512;  nkc = 16; wpo = WPO_IN; }
    else if (e < W_W1)   { src = out_w; off = e - W_OUTW; Km = 512;  nkc = 16; wpo = WPO_OUT; }
    else if (e < W_W2)   { src = w1;    off = e - W_W1;   Km = 512;  nkc = 16; wpo = WPO_W1; }
    else                 { src = w2;    off = e - W_W2;   Km = 2048; nkc = 64; wpo = WPO_W2; }
    int n = off / Km, k = off % Km;
    float4 v = *(const float4*)(src + off);
    bf16 h0,h1,h2,h3,l0,l1,l2,l3;
    split1(v.x,h0,l0); split1(v.y,h1,l1); split1(v.z,h2,l2); split1(v.w,h3,l3);
    size_t byte = wpo + ((size_t)(n >> 7) * nkc + (k >> 5)) * TILE128
                + (size_t)(n & 127) * 80 + (k & 31) * 2;
    uint2 uh, ul;
    uh.x = pack2(h0,h1); uh.y = pack2(h2,h3);
    ul.x = pack2(l0,l1); ul.y = pack2(l2,l3);
    *(uint2*)(hp + byte) = uh;
    *(uint2*)(lp + byte) = ul;
}

// ---------------- quantum projection -> padded (TB=64,K=512) ----------------
__global__ __launch_bounds__(256) void proj_kernel(const float* __restrict__ x,
                                                   uint8_t* __restrict__ ph,
                                                   uint8_t* __restrict__ pl, int ngroups) {
    int g = blockIdx.x * blockDim.x + threadIdx.x;
    if (g >= ngroups) return;
    const float4* xp = (const float4*)(x + (size_t)g * 8);
    float4 a = xp[0], b = xp[1];
    float r[8];
    r[0] = cosf(a.x);
    r[1] = r[0] * cosf(a.y);
    r[2] = r[1] * cosf(a.z);
    r[3] = r[2] * cosf(a.w);
    r[4] = r[3] * cosf(b.x);
    r[5] = r[4] * cosf(b.y);
    r[6] = r[5] * cosf(b.z);
    r[7] = r[6] * cosf(b.w);
    bf16 h[8], l[8];
#pragma unroll
    for (int i = 0; i < 8; i++) split1(r[i], h[i], l[i]);
    const int row = g >> 6;
    const int k0  = (g & 63) * 8;
    size_t byte = ((size_t)(row >> 6) * 16 + (k0 >> 5)) * TILE64
                + (size_t)(row & 63) * 80 + (k0 & 31) * 2;
    uint4 uh, ul;
    uh.x = pack2(h[0],h[1]); uh.y = pack2(h[2],h[3]);
    uh.z = pack2(h[4],h[5]); uh.w = pack2(h[6],h[7]);
    ul.x = pack2(l[0],l[1]); ul.y = pack2(l[2],l[3]);
    ul.z = pack2(l[4],l[5]); ul.w = pack2(l[6],l[7]);
    *(uint4*)(ph + byte) = uh;
    *(uint4*)(pl + byte) = ul;
}

// ---------------- 3xBF16 mma.sync GEMM, bulk-copy, 3 stages, BM=64 (2 CTAs/SM) ----------------
template<int EPI, bool RELU>
__global__ __launch_bounds__(256) void gemm_mma(
    const uint8_t* __restrict__ Aph, const uint8_t* __restrict__ Apl,
    const uint8_t* __restrict__ Bph, const uint8_t* __restrict__ Bpl,
    const float* __restrict__ bias,
    float* __restrict__ Cf, uint8_t* __restrict__ Chp, uint8_t* __restrict__ Clp,
    int N, int K)
{
    constexpr int MFRAG = 2, BM = 64;
    constexpr int ROWB = 80;
    constexpr uint32_t A_SZ = BM * ROWB;
    constexpr uint32_t B_SZ = 128 * ROWB;
    constexpr uint32_t STAGE = 2 * A_SZ + 2 * B_SZ;

    extern __shared__ char dynsmem[];
    const uint32_t hdr = smem_u32(dynsmem);
    const uint32_t dbase = hdr + 1024;

    const int tid = threadIdx.x;
    const int lane = tid & 31, wid = tid >> 5;
    const int warp_m = wid >> 2, warp_n = wid & 3;
    const int m_base = warp_m * (MFRAG * 16);
    const int n_base = warp_n * 32;
    const int blockRow = blockIdx.y * BM;
    const int blockCol = blockIdx.x * 128;
    const int T = K / 32;

    const int lg = lane >> 3, li = lane & 7;
    const int a_row = li + (lg & 1) * 8;
    const int a_col = (lg >> 1) * 8;
    const int b_row = li + (lg >> 1) * 8;
    const int b_col = (lg & 1) * 8;

    float acc[MFRAG][4][4];
#pragma unroll
    for (int mf = 0; mf < MFRAG; mf++)
#pragma unroll
        for (int nf = 0; nf < 4; nf++)
#pragma unroll
            for (int q = 0; q < 4; q++) acc[mf][nf][q] = 0.f;

    auto issue = [&](int s, int kt) {
        const uint32_t mb = hdr + (uint32_t)s * 8;
        MBAR_EXPECT_TX(mb, STAGE);
        const uint32_t sb = dbase + (uint32_t)s * STAGE;
        const uint8_t* ab = Aph + ((size_t)blockIdx.y * T + kt) * A_SZ;
        const uint8_t* al = Apl + ((size_t)blockIdx.y * T + kt) * A_SZ;
        const uint8_t* bb = Bph + ((size_t)blockIdx.x * T + kt) * B_SZ;
        const uint8_t* bl = Bpl + ((size_t)blockIdx.x * T + kt) * B_SZ;
        BULK_G2S(sb,                ab, A_SZ, mb);
        BULK_G2S(sb + A_SZ,         al, A_SZ, mb);
        BULK_G2S(sb + 2*A_SZ,       bb, B_SZ, mb);
        BULK_G2S(sb + 2*A_SZ+B_SZ,  bl, B_SZ, mb);
    };

    if (tid == 0) {
        MBAR_INIT(hdr + 0, 1u);
        MBAR_INIT(hdr + 8, 1u);
        MBAR_INIT(hdr + 16, 1u);
    }
    __syncthreads();
    if (tid == 0) { issue(0, 0); issue(1, 1); }

    for (int it = 0; it < T; ++it) {
        __syncthreads();
        if (tid == 0 && it + 2 < T) issue((it + 2) % 3, it + 2);

        const int s = it % 3;
        MBAR_WAIT(hdr + (uint32_t)s * 8, (uint32_t)((it / 3) & 1));

        const uint32_t aH = dbase + (uint32_t)s * STAGE;
        const uint32_t aL = aH + A_SZ;
        const uint32_t bH = aH + 2 * A_SZ;
        const uint32_t bL = bH + B_SZ;

        uint32_t fah[2][MFRAG][4], fal[2][MFRAG][4], fbh[2][2][4], fbl[2][2][4];
#pragma unroll
        for (int j = 0; j < 2; j++) {
#pragma unroll
            for (int mf = 0; mf < MFRAG; mf++) {
                uint32_t ro = (uint32_t)((m_base + mf * 16 + a_row) * ROWB
                                         + (j * 16 + a_col) * 2);
                ldm_x4(fah[j][mf], aH + ro);
                ldm_x4(fal[j][mf], aL + ro);
            }
#pragma unroll
            for (int nt = 0; nt < 2; nt++) {
                uint32_t ro = (uint32_t)((n_base + nt * 16 + b_row) * ROWB
                                         + (j * 16 + b_col) * 2);
                ldm_x4(fbh[j][nt], bH + ro);
                ldm_x4(fbl[j][nt], bL + ro);
            }
        }
#pragma unroll
        for (int j = 0; j < 2; j++) {
#pragma unroll
            for (int mf = 0; mf < MFRAG; mf++) {
#pragma unroll
                for (int nt = 0; nt < 2; nt++) {
#pragma unroll
                    for (int h = 0; h < 2; h++) {
                        const int nf = nt * 2 + h;
                        uint32_t bh2[2] = { fbh[j][nt][2*h], fbh[j][nt][2*h+1] };
                        uint32_t bl2[2] = { fbl[j][nt][2*h], fbl[j][nt][2*h+1] };
                        mma16816(acc[mf][nf], fah[j][mf], bh2);
                        mma16816(acc[mf][nf], fah[j][mf], bl2);
                        mma16816(acc[mf][nf], fal[j][mf], bh2);
                    }
                }
            }
        }
    }

#pragma unroll
    for (int mf = 0; mf < MFRAG; mf++) {
        const int r0 = blockRow + m_base + mf * 16 + (lane >> 2);
#pragma unroll
        for (int nf = 0; nf < 4; nf++) {
            const int col = blockCol + n_base + nf * 8 + ((lane & 3) << 1);
            const float2 bv = *(const float2*)(bias + col);
            float v0 = acc[mf][nf][0] + bv.x;
            float v1 = acc[mf][nf][1] + bv.y;
            float v2 = acc[mf][nf][2] + bv.x;
            float v3 = acc[mf][nf][3] + bv.y;
            if (RELU) {
                v0 = fmaxf(v0, 0.f); v1 = fmaxf(v1, 0.f);
                v2 = fmaxf(v2, 0.f); v3 = fmaxf(v3, 0.f);
            }
            if (EPI == 0) {
                *(float2*)(Cf + (size_t)r0 * N + col)       = make_float2(v0, v1);
                *(float2*)(Cf + (size_t)(r0 + 8) * N + col) = make_float2(v2, v3);
            } else {
                bf16 h0,h1,h2,h3,l0,l1,l2,l3;
                split1(v0,h0,l0); split1(v1,h1,l1); split1(v2,h2,l2); split1(v3,h3,l3);
                const int nkc = N >> 5;
                size_t by0 = ((size_t)(r0 >> 6) * nkc + (col >> 5)) * TILE64
                           + (size_t)(r0 & 63) * 80 + (col & 31) * 2;
                const int r1 = r0 + 8;
                size_t by1 = ((size_t)(r1 >> 6) * nkc + (col >> 5)) * TILE64
                           + (size_t)(r1 & 63) * 80 + (col & 31) * 2;
                *(uint32_t*)(Chp + by0) = pack2(h0,h1);
                *(uint32_t*)(Chp + by1) = pack2(h2,h3);
                *(uint32_t*)(Clp + by0) = pack2(l0,l1);
                *(uint32_t*)(Clp + by1) = pack2(l2,l3);
            }
        }
    }
}

// ---------------- attention part 1: key-split partial sums ----------------
// grid = (B*H)*KSPLIT, block = 512 (one thread per query). Direct-exp softmax partials.
__global__ __launch_bounds__(512) void attn_part_kernel(const float* __restrict__ qkv,
                                                        float* __restrict__ pl,
                                                        float* __restrict__ pacc) {
    const int bh = blockIdx.x / KSPLIT;
    const int ks = blockIdx.x % KSPLIT;
    const int b = bh / HH, h = bh % HH;
    __shared__ float4 Ks[KCH][2];
    __shared__ float4 Vs[KCH][2];
    const int t = threadIdx.x;
    const float* base = qkv + (size_t)b * SS * QKVN;
    const int krow0 = ks * KCH;

    if (t < 2 * KCH) {                      // 256 threads load K rows (2 halves each row)
        const int r = t >> 1, c = t & 1;
        Ks[r][c] = *(const float4*)(base + (size_t)(krow0 + r) * QKVN + EE + h * 8 + c * 4);
    } else if (t < 4 * KCH) {
        const int u = t - 2 * KCH;
        const int r = u >> 1, c = u & 1;
        Vs[r][c] = *(const float4*)(base + (size_t)(krow0 + r) * QKVN + 2 * EE + h * 8 + c * 4);
    }
    __syncthreads();

    const float sc = 0.35355339059327373f;
    float4 q0, q1;
    {
        const float* qr = base + (size_t)t * QKVN + h * 8;
        q0 = *(const float4*)qr; q1 = *(const float4*)(qr + 4);
        q0.x *= sc; q0.y *= sc; q0.z *= sc; q0.w *= sc;
        q1.x *= sc; q1.y *= sc; q1.z *= sc; q1.w *= sc;
    }

    float l = 0.f;
    float a0 = 0.f, a1 = 0.f, a2 = 0.f, a3 = 0.f;
    float a4 = 0.f, a5 = 0.f, a6 = 0.f, a7 = 0.f;
    for (int j = 0; j < KCH; j++) {
        const float4 k0 = Ks[j][0], k1 = Ks[j][1];
        float s = q0.x * k0.x + q0.y * k0.y + q0.z * k0.z + q0.w * k0.w
                + q1.x * k1.x + q1.y * k1.y + q1.z * k1.z + q1.w * k1.w;
        const float p = __expf(s);
        l += p;
        const float4 v0 = Vs[j][0], v1 = Vs[j][1];
        a0 += p * v0.x; a1 += p * v0.y; a2 += p * v0.z; a3 += p * v0.w;
        a4 += p * v1.x; a5 += p * v1.y; a6 += p * v1.z; a7 += p * v1.w;
    }
    const size_t pbase = (size_t)blockIdx.x * SS + t;
    pl[pbase] = l;
    float* pa = pacc + pbase * 8;
    *(float4*)pa       = make_float4(a0, a1, a2, a3);
    *(float4*)(pa + 4) = make_float4(a4, a5, a6, a7);
}

// ---------------- attention part 2: combine partials -> padded ctx (TB=64) ----------------
__global__ __launch_bounds__(256) void attn_comb_kernel(const float* __restrict__ pl,
                                                        const float* __restrict__ pacc,
                                                        uint8_t* __restrict__ chp,
                                                        uint8_t* __restrict__ clp) {
    const int q = blockIdx.x * blockDim.x + threadIdx.x;   // 0 .. B*H*S-1
    if (q >= BBATCH * HH * SS) return;
    const int bh = q / SS, t = q % SS;
    const int b = bh / HH, h = bh % HH;

    float l = 0.f;
    float a[8] = {0,0,0,0,0,0,0,0};
#pragma unroll
    for (int ks = 0; ks < KSPLIT; ks++) {
        const size_t pb = ((size_t)bh * KSPLIT + ks) * SS + t;
        l += pl[pb];
        const float4 v0 = *(const float4*)(pacc + pb * 8);
        const float4 v1 = *(const float4*)(pacc + pb * 8 + 4);
        a[0] += v0.x; a[1] += v0.y; a[2] += v0.z; a[3] += v0.w;
        a[4] += v1.x; a[5] += v1.y; a[6] += v1.z; a[7] += v1.w;
    }
    const float inv = 1.f / l;
    bf16 oh[8], ol[8];
#pragma unroll
    for (int d = 0; d < 8; d++) split1(a[d] * inv, oh[d], ol[d]);
    const int row = b * SS + t;
    const int k0 = h * 8;
    size_t byte = ((size_t)(row >> 6) * 16 + (k0 >> 5)) * TILE64
                + (size_t)(row & 63) * 80 + (k0 & 31) * 2;
    uint4 uh, ul;
    uh.x = pack2(oh[0],oh[1]); uh.y = pack2(oh[2],oh[3]);
    uh.z = pack2(oh[4],oh[5]); uh.w = pack2(oh[6],oh[7]);
    ul.x = pack2(ol[0],ol[1]); ul.y = pack2(ol[2],ol[3]);
    ul.z = pack2(ol[4],ol[5]); ul.w = pack2(ol[6],ol[7]);
    *(uint4*)(chp + byte) = uh;
    *(uint4*)(clp + byte) = ul;
}

// ---------------- fused residual add + layernorm; SPLIT -> padded (TB=64, K=512) ----------------
template<bool SPLIT>
__global__ __launch_bounds__(128) void add_ln_kernel(const float* __restrict__ a,
                                                     const float* __restrict__ r,
                                                     const float* __restrict__ w,
                                                     const float* __restrict__ bb,
                                                     float* __restrict__ out,
                                                     uint8_t* __restrict__ ohp,
                                                     uint8_t* __restrict__ olp) {
    const int row = blockIdx.x;
    const int t = threadIdx.x;
    const float4 av = ((const float4*)(a + (size_t)row * EE))[t];
    const float4 rv = ((const float4*)(r + (size_t)row * EE))[t];
    float v0 = av.x + rv.x, v1 = av.y + rv.y, v2 = av.z + rv.z, v3 = av.w + rv.w;

    __shared__ float sh[4];
    __shared__ float sh2[4];
    float s = v0 + v1 + v2 + v3;
#pragma unroll
    for (int o = 16; o; o >>= 1) s += __shfl_xor_sync(0xffffffffu, s, o);
    if ((t & 31) == 0) sh[t >> 5] = s;
    __syncthreads();
    const float mean = (sh[0] + sh[1] + sh[2] + sh[3]) * (1.f / 512.f);

    float d0 = v0 - mean, d1 = v1 - mean, d2 = v2 - mean, d3 = v3 - mean;
    float qsum = d0*d0 + d1*d1 + d2*d2 + d3*d3;
#pragma unroll
    for (int o = 16; o; o >>= 1) qsum += __shfl_xor_sync(0xffffffffu, qsum, o);
    if ((t & 31) == 0) sh2[t >> 5] = qsum;
    __syncthreads();
    const float var = (sh2[0] + sh2[1] + sh2[2] + sh2[3]) * (1.f / 512.f);
    const float inv = rsqrtf(var + 1e-5f);

    const float4 wv = ((const float4*)w)[t];
    const float4 bv = ((const float4*)bb)[t];
    float o0 = d0 * inv * wv.x + bv.x;
    float o1 = d1 * inv * wv.y + bv.y;
    float o2 = d2 * inv * wv.z + bv.z;
    float o3 = d3 * inv * wv.w + bv.w;
    ((float4*)(out + (size_t)row * EE))[t] = make_float4(o0, o1, o2, o3);
    if (SPLIT) {
        bf16 h0,h1,h2,h3,l0,l1,l2,l3;
        split1(o0,h0,l0); split1(o1,h1,l1); split1(o2,h2,l2); split1(o3,h3,l3);
        const int k0 = t * 4;
        size_t byte = ((size_t)(row >> 6) * 16 + (k0 >> 5)) * TILE64
                    + (size_t)(row & 63) * 80 + (k0 & 31) * 2;
        uint2 uh, ul;
        uh.x = pack2(h0,h1); uh.y = pack2(h2,h3);
        ul.x = pack2(l0,l1); ul.y = pack2(l2,l3);
        *(uint2*)(ohp + byte) = uh;
        *(uint2*)(olp + byte) = ul;
    }
}

// ---------------- host launch ----------------
#define SMEMB (1024 + 3 * (2 * (64*80) + 2 * (128*80)))

extern "C" void kernel_launch(void* const* d_in, const int* in_sizes, int n_in,
                              void* d_out, int out_size) {
    const float* x     = (const float*)d_in[0];
    const float* in_w  = (const float*)d_in[1];
    const float* in_b  = (const float*)d_in[2];
    const float* out_w = (const float*)d_in[3];
    const float* out_b = (const float*)d_in[4];
    const float* ln1w  = (const float*)d_in[5];
    const float* ln1b  = (const float*)d_in[6];
    const float* ln2w  = (const float*)d_in[7];
    const float* ln2b  = (const float*)d_in[8];
    const float* w1    = (const float*)d_in[9];
    const float* b1    = (const float*)d_in[10];
    const float* w2    = (const float*)d_in[11];
    const float* b2    = (const float*)d_in[12];
    float* out = (float*)d_out;

    static uint8_t *pp_h=nullptr, *pp_l, *pc_h, *pc_l, *px_h, *px_l, *ph_h, *ph_l, *pw_h, *pw_l;
    static float *p_qkv, *p_x1f, *p_t0, *p_pl, *p_pacc;
    if (!pp_h) {
        cudaGetSymbolAddress((void**)&pp_h, g_pa_proj_h);
        cudaGetSymbolAddress((void**)&pp_l, g_pa_proj_l);
        cudaGetSymbolAddress((void**)&pc_h, g_pa_ctx_h);
        cudaGetSymbolAddress((void**)&pc_l, g_pa_ctx_l);
        cudaGetSymbolAddress((void**)&px_h, g_pa_x1_h);
        cudaGetSymbolAddress((void**)&px_l, g_pa_x1_l);
        cudaGetSymbolAddress((void**)&ph_h, g_pa_h_h);
        cudaGetSymbolAddress((void**)&ph_l, g_pa_h_l);
        cudaGetSymbolAddress((void**)&pw_h, g_wp_h);
        cudaGetSymbolAddress((void**)&pw_l, g_wp_l);
        cudaGetSymbolAddress((void**)&p_qkv, g_qkv);
        cudaGetSymbolAddress((void**)&p_x1f, g_x1f);
        cudaGetSymbolAddress((void**)&p_t0,  g_t0);
        cudaGetSymbolAddress((void**)&p_pl,  g_pl);
        cudaGetSymbolAddress((void**)&p_pacc, g_pacc);
        cudaFuncSetAttribute(gemm_mma<0,false>, cudaFuncAttributeMaxDynamicSharedMemorySize, SMEMB);
        cudaFuncSetAttribute(gemm_mma<1,true >, cudaFuncAttributeMaxDynamicSharedMemorySize, SMEMB);
    }

    // weight splits -> padded tiles
    split_all_kernel<<<(W_TOTAL/4 + 255)/256, 256>>>(in_w, out_w, w1, w2, pw_h, pw_l);

    // proj -> padded tiles (TB=64)
    const int ngroups = MROWS * EE / 8;
    proj_kernel<<<(ngroups + 255)/256, 256>>>(x, pp_h, pp_l, ngroups);

    // qkv = proj @ in_w^T + in_b  (2048 x 1536, K=512) -> fp32 linear
    gemm_mma<0,false><<<dim3(QKVN/128, MROWS/64), 256, SMEMB>>>(
        pp_h, pp_l, pw_h + WPO_IN, pw_l + WPO_IN, in_b,
        p_qkv, nullptr, nullptr, QKVN, EE);

    // attention: key-split partials, then combine -> ctx padded (TB=64)
    attn_part_kernel<<<BBATCH * HH * KSPLIT, 512>>>(p_qkv, p_pl, p_pacc);
    attn_comb_kernel<<<(BBATCH * HH * SS + 255) / 256, 256>>>(p_pl, p_pacc, pc_h, pc_l);

    // attn_out = ctx @ out_w^T + out_b (2048 x 512, K=512) -> t0 fp32
    gemm_mma<0,false><<<dim3(EE/128, MROWS/64), 256, SMEMB>>>(
        pc_h, pc_l, pw_h + WPO_OUT, pw_l + WPO_OUT, out_b,
        p_t0, nullptr, nullptr, EE, EE);

    // x1 = LN(x + attn_out) -> fp32 + padded hi/lo (TB=64)
    add_ln_kernel<true><<<MROWS, 128>>>(x, p_t0, ln1w, ln1b, p_x1f, px_h, px_l);

    // h = relu(x1 @ w1^T + b1) (2048 x 2048, K=512) -> padded hi/lo (TB=64, K_out=2048)
    gemm_mma<1,true><<<dim3(FFNN/128, MROWS/64), 256, SMEMB>>>(
        px_h, px_l, pw_h + WPO_W1, pw_l + WPO_W1, b1,
        nullptr, ph_h, ph_l, FFNN, EE);

    // ffn_out = h @ w2^T + b2 (2048 x 512, K=2048) -> t0 fp32
    gemm_mma<0,false><<<dim3(EE/128, MROWS/64), 256, SMEMB>>>(
        ph_h, ph_l, pw_h + WPO_W2, pw_l + WPO_W2, b2,
        p_t0, nullptr, nullptr, EE, FFNN);

    // out = LN(x1 + ffn_out)
    add_ln_kernel<false><<<MROWS, 128>>>(p_x1f, p_t0, ln2w, ln2b, out, nullptr, nullptr);

    (void)in_sizes; (void)n_in; (void)out_size;
}